// round 12
// baseline (speedup 1.0000x reference)
#include <cuda_runtime.h>
#include <stdint.h>
#include <limits.h>

#define TPB 256
#define BE1 2048          // elements per k1 block (two 1024-halves)
#define BE3 1024          // elements per k3 block
#define NBMAX 4096
#define NMAX  4194304
#define FULLM 0xffffffffu

// ---------------- device scratch (no allocations allowed) ----------------
__device__ float g_cp[NMAX];      // combined prob (pre-shift), written by k1, read by k3
__device__ int   g_qh[64];
__device__ int   g_mich[64];
__device__ int   g_shellh[7];
__device__ int   g_famh[4];
__device__ int   g_blkV[NBMAX];   // valid count per 1024-element half-block
__device__ float g_blkC[NBMAX];   // csum per k1 block (2048 elems)
__device__ int   g_vpfx[NBMAX];   // exclusive valid prefix per 1024-element half-block
__device__ int   g_look[NBMAX];   // lookback words: 0=empty, (v<<2)|1=aggregate, (v<<2)|2=inclusive
__device__ int   g_pc;            // global boundary count accumulator
__device__ float g_E;             // exp(shift)
__device__ float g_cpT;           // sigmoid(-shift): bmask <=> cp >= g_cpT
__device__ int   g_totValid;

// ---------------- K1 tile worker (1 float4/int4 tile, fully coalesced) ----------------
__device__ __forceinline__ void tileWork(
    int i0, int n, int lane,
    const float* __restrict__ lp, const int* __restrict__ st,
    const int* __restrict__ q,  const int* __restrict__ fam,
    const int* __restrict__ mic, const int* __restrict__ vm,
    float* __restrict__ outStruct,
    float& csum, int& vcnt,
    unsigned long long& facc, unsigned long long& shacc,
    unsigned char* myh, int lbase)
{
    int4   s4 = __ldg((const int4*)(st  + i0));
    int4   q4 = __ldg((const int4*)(q   + i0));
    int4   f4 = __ldg((const int4*)(fam + i0));
    int4   m4 = __ldg((const int4*)(mic + i0));
    float4 l4 = __ldg((const float4*)(lp + i0));
    int4   v4 = __ldg((const int4*)(vm  + i0));

    // neighbor (element i0+4) via warp shuffle; lane 31 loads from global
    int sn = __shfl_down_sync(FULLM, s4.x, 1);
    int qn = __shfl_down_sync(FULLM, q4.x, 1);
    int fn = __shfl_down_sync(FULLM, f4.x, 1);
    int nsi = i0 + 4;
    if (lane == 31) {
        bool inr = (nsi < n);
        sn = inr ? __ldg(st  + nsi) : 0;
        qn = inr ? __ldg(q   + nsi) : 0;
        fn = inr ? __ldg(fam + nsi) : 0;
    }

    int   sa[5] = { s4.x, s4.y, s4.z, s4.w, sn };
    int   qa[5] = { q4.x, q4.y, q4.z, q4.w, qn };
    int   fa[5] = { f4.x, f4.y, f4.z, f4.w, fn };
    int   ma[4] = { m4.x, m4.y, m4.z, m4.w };
    float la[4] = { l4.x, l4.y, l4.z, l4.w };
    int   va[4] = { v4.x, v4.y, v4.z, v4.w };

    float so[4], cpo[4];
    #pragma unroll
    for (int k = 0; k < 4; k++) {
        int c6  = ((sa[k]   >> 6) ^ sa[k]  ) & 63;
        int c6n = ((sa[k+1] >> 6) ^ sa[k+1]) & 63;
        float d_chi = (float)__popc(c6 ^ c6n) / 6.0f;
        float d_q   = (float)__popc((qa[k] & 63) ^ (qa[k+1] & 63)) / 6.0f;
        float d_f   = (float)__popc((fa[k] ^ fa[k+1]) & 3) * 0.5f;
        float score = 0.5f*d_chi + 0.35f*d_q + 0.15f*d_f;
        score = fminf(fmaxf(score, 1e-6f), 1.0f);
        bool v = (va[k] != 0);
        so[k] = v ? score : 0.0f;
        float cosine = expf(fminf(la[k], 0.0f));   // accurate expf: feeds threshold path
        float cpv = 0.5f*cosine + 0.5f*so[k];
        cpo[k] = cpv;
        if (v) {
            csum += cpv;
            vcnt++;
            int qb = qa[k] & 63;
            int aq = ((qb >> 3) << 7) + lbase + ((qb >> 1) & 3);
            myh[aq] = (unsigned char)(myh[aq] + (1 << ((qb & 1) << 2)));
            int mb = ma[k] & 63;
            int am = 1024 + ((mb >> 3) << 7) + lbase + ((mb >> 1) & 3);
            myh[am] = (unsigned char)(myh[am] + (1 << ((mb & 1) << 2)));
            facc  += 1ull << ((fa[k] & 3) << 4);
            shacc += 1ull << (__popc(c6) * 9);
        }
    }
    *(float4*)(outStruct + i0) = make_float4(so[0], so[1], so[2], so[3]);
    *(float4*)(g_cp + i0)      = make_float4(cpo[0], cpo[1], cpo[2], cpo[3]);
}

// ---------------- K1: structural + cp + atomic-free histograms (2 tiles/thread) ----------------
__global__ __launch_bounds__(TPB) void k1(
    const float* __restrict__ lp, const int* __restrict__ st,
    const int* __restrict__ q,  const int* __restrict__ fam,
    const int* __restrict__ mic, const int* __restrict__ vm,
    float* __restrict__ outStruct, int n)
{
    __shared__ unsigned char wb[8][2048];
    __shared__ int blkH[128];
    __shared__ int sShell[7];
    __shared__ float swC[8];
    __shared__ int   swV[8];
    __shared__ unsigned long long swF[8];

    int t = threadIdx.x, lane = t & 31, wid = t >> 5;
    {   // zero 16KB of nibble counters + small arrays
        unsigned* w32 = (unsigned*)wb;
        #pragma unroll
        for (int i = 0; i < 16; i++) w32[t + i*TPB] = 0u;
        if (t < 128) blkH[t] = 0;
        if (t < 7)   sShell[t] = 0;
    }
    __syncthreads();

    int b = blockIdx.x;
    unsigned char* myh = wb[wid];
    int lbase = lane << 2;

    float csum = 0.f;
    unsigned long long facc = 0ull, shacc = 0ull;
    int vcnt0 = 0, vcnt1 = 0;

    tileWork(b*BE1        + t*4, n, lane, lp, st, q, fam, mic, vm, outStruct,
             csum, vcnt0, facc, shacc, myh, lbase);
    tileWork(b*BE1 + 1024 + t*4, n, lane, lp, st, q, fam, mic, vm, outStruct,
             csum, vcnt1, facc, shacc, myh, lbase);

    __syncwarp();
    // per-warp nibble-hist flush (2x16 split keeps per-byte partials <= 128)
    if (lane < 16) {
        const unsigned* wrow = (const unsigned*)wb[wid];
        int rbase = lane * 32;
        unsigned loA = 0u, hiA = 0u, loB = 0u, hiB = 0u;
        #pragma unroll
        for (int w = 0; w < 16; w++) {
            unsigned u = wrow[rbase + ((w + lane) & 31)];
            loA += u & 0x0F0F0F0Fu;
            hiA += (u >> 4) & 0x0F0F0F0Fu;
        }
        #pragma unroll
        for (int w = 16; w < 32; w++) {
            unsigned u = wrow[rbase + ((w + lane) & 31)];
            loB += u & 0x0F0F0F0Fu;
            hiB += (u >> 4) & 0x0F0F0F0Fu;
        }
        int off = (lane < 8) ? 0 : 64;
        int group = lane & 7;
        #pragma unroll
        for (int c = 0; c < 4; c++) {
            int lo = (int)((loA >> (8*c)) & 0xff) + (int)((loB >> (8*c)) & 0xff);
            int hi = (int)((hiA >> (8*c)) & 0xff) + (int)((hiB >> (8*c)) & 0xff);
            atomicAdd(&blkH[off + group*8 + c*2 + 0], lo);
            atomicAdd(&blkH[off + group*8 + c*2 + 1], hi);
        }
    }

    // deterministic per-block reductions (fixed order; csum path deterministic)
    int vpack = vcnt0 | (vcnt1 << 16);
    #pragma unroll
    for (int o = 16; o; o >>= 1) {
        csum  += __shfl_down_sync(FULLM, csum,  o);
        vpack += __shfl_down_sync(FULLM, vpack, o);
        facc  += __shfl_down_sync(FULLM, facc,  o);
        shacc += __shfl_down_sync(FULLM, shacc, o);
    }
    if (lane == 0) {
        swC[wid] = csum; swV[wid] = vpack; swF[wid] = facc;
        #pragma unroll
        for (int f = 0; f < 7; f++) {
            int c = (int)((shacc >> (9*f)) & 511ull);
            if (c) atomicAdd(&sShell[f], c);
        }
    }
    __syncthreads();

    // global flush
    if (t < 128) {
        int c = blkH[t];
        if (c) atomicAdd((t < 64) ? &g_qh[t] : &g_mich[t - 64], c);
    }
    if (t < 7) {
        int c = sShell[t];
        if (c) atomicAdd(&g_shellh[t], c);
    }
    if (t == 0) {
        float cs = 0.f; int vp = 0; unsigned long long fs = 0ull;
        for (int w = 0; w < 8; w++) { cs += swC[w]; vp += swV[w]; fs += swF[w]; }
        g_blkC[b] = cs;
        g_blkV[2*b]     = vp & 0xffff;
        g_blkV[2*b + 1] = (vp >> 16) & 0xffff;
        atomicAdd(&g_famh[0], (int)( fs        & 0xffff));
        atomicAdd(&g_famh[1], (int)((fs >> 16) & 0xffff));
        atomicAdd(&g_famh[2], (int)((fs >> 32) & 0xffff));
        atomicAdd(&g_famh[3], (int)((fs >> 48) & 0xffff));
    }
}

// ---------------- K2: 1024 thr, shuffle vpfx scan (int4) + bit-identical csum tree ----------------
__global__ __launch_bounds__(1024) void k2(float* __restrict__ out, int n, int NB1, int NBV) {
    __shared__ int sScan[32];
    __shared__ float sf[1024];
    int t = threadIdx.x, lane = t & 31, wid = t >> 5;

    // zero lookback state + patch counter for the upcoming k3 (replay-safe)
    {
        int z0 = 4*t;
        if (z0 + 3 < NBMAX) *(int4*)(g_look + z0) = make_int4(0, 0, 0, 0);
        if (t == 0) g_pc = 0;
    }

    // (a) integer vpfx scan: 4 contiguous half-blocks per thread, int4 loads
    int4 v4;
    int bi0 = 4*t;
    if (bi0 + 3 < NBV) {
        v4 = *(const int4*)(g_blkV + bi0);
    } else {
        v4.x = (bi0+0 < NBV) ? g_blkV[bi0+0] : 0;
        v4.y = (bi0+1 < NBV) ? g_blkV[bi0+1] : 0;
        v4.z = (bi0+2 < NBV) ? g_blkV[bi0+2] : 0;
        v4.w = (bi0+3 < NBV) ? g_blkV[bi0+3] : 0;
    }
    int tsum = v4.x + v4.y + v4.z + v4.w;
    int incl = tsum;
    #pragma unroll
    for (int d = 1; d < 32; d <<= 1) {
        int o = __shfl_up_sync(FULLM, incl, d);
        if (lane >= d) incl += o;
    }
    if (lane == 31) sScan[wid] = incl;
    __syncthreads();
    if (wid == 0) {
        int x = sScan[lane];
        #pragma unroll
        for (int d = 1; d < 32; d <<= 1) {
            int o = __shfl_up_sync(FULLM, x, d);
            if (lane >= d) x += o;
        }
        sScan[lane] = x;   // inclusive scan of warp sums
    }
    __syncthreads();
    int woff = wid ? sScan[wid - 1] : 0;
    int run = woff + incl - tsum;
    if (bi0 + 3 < NBV) {
        int4 o4;
        o4.x = run; run += v4.x;
        o4.y = run; run += v4.y;
        o4.z = run; run += v4.z;
        o4.w = run;
        *(int4*)(g_vpfx + bi0) = o4;
    } else {
        if (bi0+0 < NBV) g_vpfx[bi0+0] = run; run += v4.x;
        if (bi0+1 < NBV) g_vpfx[bi0+1] = run; run += v4.y;
        if (bi0+2 < NBV) g_vpfx[bi0+2] = run; run += v4.z;
        if (bi0+3 < NBV) g_vpfx[bi0+3] = run;
    }
    int total = sScan[31];

    // (b) csum tree — BIT-IDENTICAL to the validated 1024-slot pairwise tree
    {
        int b0 = 2*t, b1 = 2*t + 1;
        float c2 = 0.f;
        if (b0 < NB1) c2 += g_blkC[b0];
        if (b1 < NB1) c2 += g_blkC[b1];
        sf[t] = c2;
    }
    __syncthreads();
    for (int d = 512; d; d >>= 1) { if (t < d) sf[t] += sf[t + d]; __syncthreads(); }

    if (t == 0) {
        g_totValid = total;
        float vcf = fmaxf((float)total, 1.0f);
        float cur = sf[0] / vcf;
        cur = fminf(fmaxf(cur, 1e-4f), 1.0f - 1e-4f);
        float tgt = 1.0f / 6.0f;  // 1 / TARGET_BPP (within clip range)
        float shift = (logf(tgt) - log1pf(-tgt)) - (logf(cur) - log1pf(-cur));
        g_E = expf(shift);
        g_cpT = (float)(1.0 / (1.0 + exp((double)shift)));   // sigmoid(-shift)
    }

    // (c) small-hist outputs (K1 fully done before K2 in stream order)
    float* H = out + 3 * (size_t)n;
    if (t < 64)              H[t] = (float)g_qh[t];
    if (t >= 64 && t < 68)   H[t] = (float)g_famh[t - 64];
    if (t >= 128 && t < 192) H[68 + (t - 128)] = (float)g_mich[t - 128];
    if (t >= 256 && t < 263) H[132 + (t - 256)] = (float)g_shellh[t - 256];
    if (t >= 288 && t < 295) {            // q_weight_hist7 from q hist
        int w = t - 288, acc2 = 0;
        for (int qq = 0; qq < 64; qq++) if (__popc(qq) == w) acc2 += g_qh[qq];
        H[139 + w] = (float)acc2;
    }
    if (t >= 320 && t < 326) {            // bit_excitation6 from q hist
        int j = t - 320, acc2 = 0;
        for (int qq = 0; qq < 64; qq++) acc2 += g_qh[qq] * ((qq >> j) & 1);
        H[146 + j] = (float)acc2;
    }
}

// ---------------- K3: logprobs, bmask, lengths with decoupled-lookback carry ----------------
__global__ __launch_bounds__(TPB, 8) void k3(
    const int* __restrict__ vm,
    float* __restrict__ outCL, float* __restrict__ outBM, float* __restrict__ outLen,
    float* __restrict__ out, int n, int NBV)
{
    __shared__ int swS[8], swM[8], swB[8];
    __shared__ int s_carry;
    int t = threadIdx.x, b = blockIdx.x;
    int lane = t & 31, wid = t >> 5;
    int i0 = b * BE3 + t * 4;
    float E   = g_E;
    float cpT = g_cpT;
    int vOff = g_vpfx[b];

    // valid bitmask for my 4 elements (valid_mask stored as int32)
    int4 vv = __ldg((const int4*)(vm + i0));
    unsigned vmask = 0;
    if (vv.x) vmask |= 1u;
    if (vv.y) vmask |= 2u;
    if (vv.z) vmask |= 4u;
    if (vv.w) vmask |= 8u;

    int tsum = __popc(vmask);
    int incl = tsum;
    #pragma unroll
    for (int d = 1; d < 32; d <<= 1) {
        int o = __shfl_up_sync(FULLM, incl, d);
        if (lane >= d) incl += o;
    }
    if (lane == 31) swS[wid] = incl;

    // lean math: sigmoid(logit(cp)+shift) == cp*E / (cp*E + 1-cp); bmask via cp >= cpT
    float4 c4 = __ldg((const float4*)(g_cp + i0));
    float ca[4] = { c4.x, c4.y, c4.z, c4.w };
    float clo[4], bmo[4];
    unsigned bvmask = 0;
    #pragma unroll
    for (int k = 0; k < 4; k++) {
        float cpc = fminf(fmaxf(ca[k], 1e-6f), 1.0f - 1e-6f);
        float a = cpc * E;
        float cb = __fdividef(a, a + (1.0f - cpc));
        cb = fminf(fmaxf(cb, 1e-6f), 1.0f - 1e-6f);
        clo[k] = __logf(cb);
        bool bm = (cpc >= cpT);          // exact monotone equivalent of cl >= log(0.5)
        bmo[k] = bm ? 1.0f : 0.0f;
        if (bm && ((vmask >> k) & 1)) bvmask |= 1u << k;
    }
    *(float4*)(outCL + i0) = make_float4(clo[0], clo[1], clo[2], clo[3]);
    *(float4*)(outBM + i0) = make_float4(bmo[0], bmo[1], bmo[2], bmo[3]);

    __syncthreads();   // S1: swS visible
    int blkE = 0;
    for (int w = 0; w < wid; w++) blkE += swS[w];
    int posExcl = vOff + blkE + (incl - tsum);

    // last boundary pos in my segment (pos is nondecreasing => max == last)
    int tlast = 0;
    if (bvmask) {
        int kb = 31 - __clz(bvmask);
        tlast = posExcl + __popc(vmask & ((2u << kb) - 1));
    }
    int im = tlast;
    #pragma unroll
    for (int d = 1; d < 32; d <<= 1) {
        int o = __shfl_up_sync(FULLM, im, d);
        if (lane >= d) im = max(im, o);
    }
    // shuffle executed unconditionally by ALL lanes; select afterwards
    int texm_raw = __shfl_up_sync(FULLM, im, 1);
    int texm = (lane == 0) ? 0 : texm_raw;
    if (lane == 31) swM[wid] = im;

    int bc = __popc(bvmask);
    #pragma unroll
    for (int o = 16; o; o >>= 1) bc += __shfl_down_sync(FULLM, bc, o);
    if (lane == 0) swB[wid] = bc;

    __syncthreads();   // S2: swM, swB visible

    // ---- warp 0: publish aggregate, decoupled lookback, publish inclusive ----
    if (wid == 0) {
        int bl = 0, bcnt = 0;
        #pragma unroll
        for (int w = 0; w < 8; w++) { bl = max(bl, swM[w]); bcnt += swB[w]; }
        if (lane == 0) {
            atomicAdd(&g_pc, bcnt);
            __threadfence();
            atomicExch(&g_look[b], (bl << 2) | 1);   // aggregate (fence orders g_pc add first)
        }
        __syncwarp();
        int carry = 0;
        int p = b - 1;
        while (p >= 0) {
            int idx = p - lane;
            int v = (idx >= 0) ? *(volatile int*)&g_look[idx] : 2;   // sentinel: inclusive 0
            unsigned incm  = __ballot_sync(FULLM, (v & 2) != 0);
            unsigned zerom = __ballot_sync(FULLM, v == 0);
            if (incm) {
                int fi = __ffs(incm) - 1;                 // newest inclusive in window
                if (!(zerom & ((1u << fi) - 1))) {        // all newer entries published
                    int val = (lane <= fi) ? (v >> 2) : 0;
                    #pragma unroll
                    for (int o = 16; o; o >>= 1) val = max(val, __shfl_down_sync(FULLM, val, o));
                    carry = max(carry, __shfl_sync(FULLM, val, 0));
                    break;
                }
            } else if (!zerom) {
                int val = v >> 2;                         // window of aggregates only
                #pragma unroll
                for (int o = 16; o; o >>= 1) val = max(val, __shfl_down_sync(FULLM, val, o));
                carry = max(carry, __shfl_sync(FULLM, val, 0));
                p -= 32;
            }
            // else: re-poll (unpublished predecessors in window)
        }
        if (lane == 0) {
            int inc = max(carry, bl);
            atomicExch(&g_look[b], (inc << 2) | 2);       // inclusive
            s_carry = carry;
            if (b == NBV - 1) {
                // all predecessors' g_pc adds visible (fence-before-publish, inductively)
                int tv = g_totValid;
                int trailing = tv - inc;                  // inc == global cummax
                int pcs = atomicAdd(&g_pc, 0);
                out[4 * (size_t)n + 152] = (float)trailing;
                out[4 * (size_t)n + 153] = (float)(pcs + (trailing > 0 ? 1 : 0));
            }
        }
    }
    __syncthreads();   // S3: s_carry visible

    int blkM = 0;
    for (int w = 0; w < wid; w++) blkM = max(blkM, swM[w]);
    int running = max(max(blkM, texm), s_carry);   // true exclusive prev incl. global carry

    float lo[4];
    #pragma unroll
    for (int k = 0; k < 4; k++) {
        float lenv = 0.0f;
        if ((bvmask >> k) & 1) {
            int posk = posExcl + __popc(vmask & ((2u << k) - 1));
            lenv = (float)(posk - running);
            running = posk;
        }
        lo[k] = lenv;
    }
    // outLen base pointer is offset by 152 floats (not 16B aligned) -> scalar stores
    outLen[i0+0] = lo[0]; outLen[i0+1] = lo[1]; outLen[i0+2] = lo[2]; outLen[i0+3] = lo[3];

    // last block re-zeroes global hist accumulators for the next graph replay
    // (hists are only read by k2, which runs before any k3 of the next call)
    if (b == NBV - 1) {
        if (t < 64) { g_qh[t] = 0; g_mich[t] = 0; }
        if (t < 7)  g_shellh[t] = 0;
        if (t < 4)  g_famh[t] = 0;
    }
}

// ---------------- launch ----------------
extern "C" void kernel_launch(void* const* d_in, const int* in_sizes, int n_in,
                              void* d_out, int out_size) {
    const float* lp = (const float*)d_in[0];
    const int* st   = (const int*)d_in[1];
    const int* q    = (const int*)d_in[2];
    const int* fam  = (const int*)d_in[3];
    const int* mic  = (const int*)d_in[4];
    const int* vm   = (const int*)d_in[5];   // bool promoted to int32 by harness
    float* out = (float*)d_out;
    int n = in_sizes[0];            // 4194304
    int NB1 = (n + BE1 - 1) / BE1;  // 2048 k1 blocks
    int NBV = NB1 * 2;              // 4096 half-blocks (= k3 blocks)

    k1<<<NB1, TPB>>>(lp, st, q, fam, mic, vm, out + 2 * (size_t)n, n);
    k2<<<1, 1024>>>(out, n, NB1, NBV);
    k3<<<NBV, TPB>>>(vm, out, out + (size_t)n, out + 3 * (size_t)n + 152, out, n, NBV);
}

// round 13
// speedup vs baseline: 1.1517x; 1.1517x over previous
#include <cuda_runtime.h>
#include <stdint.h>
#include <limits.h>

#define TPB 256
#define BE1 2048          // elements per k1 block (two 1024-halves)
#define BE3 1024          // elements per k3 block
#define NBMAX 4096
#define NMAX  4194304
#define FULLM 0xffffffffu

// ---------------- device scratch (no allocations allowed) ----------------
__device__ float g_cp[NMAX];      // combined prob (pre-shift), written by k1, read by k3
__device__ int   g_qh[64];
__device__ int   g_mich[64];
__device__ int   g_shellh[7];
__device__ int   g_famh[4];
__device__ int   g_blkV[NBMAX];   // valid count per 1024-element half-block
__device__ float g_blkC[NBMAX];   // csum per k1 block (2048 elems)
__device__ int   g_vpfx[NBMAX];   // exclusive valid prefix per 1024-element half-block
__device__ int   g_blkLast[NBMAX];
__device__ int   g_blkFirstIdx[NBMAX];
__device__ int   g_blkFirstPos[NBMAX];
__device__ int   g_blkBvCnt[NBMAX];
__device__ float g_E;             // exp(shift)
__device__ float g_cpT;           // sigmoid(-shift): bmask <=> cp >= g_cpT
__device__ int   g_totValid;

// ---------------- K1 tile worker (1 float4/int4 tile, fully coalesced) ----------------
__device__ __forceinline__ void tileWork(
    int i0, int n, int lane,
    const float* __restrict__ lp, const int* __restrict__ st,
    const int* __restrict__ q,  const int* __restrict__ fam,
    const int* __restrict__ mic, const int* __restrict__ vm,
    float* __restrict__ outStruct,
    float& csum, int& vpack, int vinc,
    unsigned long long& facc, unsigned long long& shacc,
    unsigned char* myh, int lbase)
{
    int4   s4 = __ldg((const int4*)(st  + i0));
    int4   q4 = __ldg((const int4*)(q   + i0));
    int4   f4 = __ldg((const int4*)(fam + i0));
    int4   m4 = __ldg((const int4*)(mic + i0));
    float4 l4 = __ldg((const float4*)(lp + i0));
    int4   v4 = __ldg((const int4*)(vm  + i0));

    // neighbor (element i0+4) via warp shuffle; lane 31 loads from global
    int sn = __shfl_down_sync(FULLM, s4.x, 1);
    int qn = __shfl_down_sync(FULLM, q4.x, 1);
    int fn = __shfl_down_sync(FULLM, f4.x, 1);
    int nsi = i0 + 4;
    if (lane == 31) {
        bool inr = (nsi < n);
        sn = inr ? __ldg(st  + nsi) : 0;
        qn = inr ? __ldg(q   + nsi) : 0;
        fn = inr ? __ldg(fam + nsi) : 0;
    }

    int   sa[5] = { s4.x, s4.y, s4.z, s4.w, sn };
    int   qa[5] = { q4.x, q4.y, q4.z, q4.w, qn };
    int   fa[5] = { f4.x, f4.y, f4.z, f4.w, fn };
    int   ma[4] = { m4.x, m4.y, m4.z, m4.w };
    float la[4] = { l4.x, l4.y, l4.z, l4.w };
    int   va[4] = { v4.x, v4.y, v4.z, v4.w };

    float so[4], cpo[4];
    #pragma unroll
    for (int k = 0; k < 4; k++) {
        int c6  = ((sa[k]   >> 6) ^ sa[k]  ) & 63;
        int c6n = ((sa[k+1] >> 6) ^ sa[k+1]) & 63;
        float d_chi = (float)__popc(c6 ^ c6n) / 6.0f;
        float d_q   = (float)__popc((qa[k] & 63) ^ (qa[k+1] & 63)) / 6.0f;
        float d_f   = (float)__popc((fa[k] ^ fa[k+1]) & 3) * 0.5f;
        float score = 0.5f*d_chi + 0.35f*d_q + 0.15f*d_f;
        score = fminf(fmaxf(score, 1e-6f), 1.0f);
        bool v = (va[k] != 0);
        so[k] = v ? score : 0.0f;
        float cosine = expf(fminf(la[k], 0.0f));   // accurate expf: feeds threshold path
        float cpv = 0.5f*cosine + 0.5f*so[k];
        cpo[k] = cpv;
        if (v) {
            csum += cpv;
            vpack += vinc;
            int qb = qa[k] & 63;
            int aq = ((qb >> 3) << 7) + lbase + ((qb >> 1) & 3);
            myh[aq] = (unsigned char)(myh[aq] + (1 << ((qb & 1) << 2)));
            int mb = ma[k] & 63;
            int am = 1024 + ((mb >> 3) << 7) + lbase + ((mb >> 1) & 3);
            myh[am] = (unsigned char)(myh[am] + (1 << ((mb & 1) << 2)));
            facc  += 1ull << ((fa[k] & 3) << 4);
            shacc += 1ull << (__popc(c6) * 9);
        }
    }
    *(float4*)(outStruct + i0) = make_float4(so[0], so[1], so[2], so[3]);
    *(float4*)(g_cp + i0)      = make_float4(cpo[0], cpo[1], cpo[2], cpo[3]);
}

// ---------------- K1: structural + cp + atomic-free histograms (2 tiles/thread) ----------------
__global__ __launch_bounds__(TPB, 5) void k1(
    const float* __restrict__ lp, const int* __restrict__ st,
    const int* __restrict__ q,  const int* __restrict__ fam,
    const int* __restrict__ mic, const int* __restrict__ vm,
    float* __restrict__ outStruct, int n)
{
    __shared__ unsigned char wb[8][2048];
    __shared__ int blkH[128];
    __shared__ int sShell[7];
    __shared__ float swC[8];
    __shared__ int   swV[8];
    __shared__ unsigned long long swF[8];

    int t = threadIdx.x, lane = t & 31, wid = t >> 5;
    {   // zero 16KB of nibble counters + small arrays
        unsigned* w32 = (unsigned*)wb;
        #pragma unroll
        for (int i = 0; i < 16; i++) w32[t + i*TPB] = 0u;
        if (t < 128) blkH[t] = 0;
        if (t < 7)   sShell[t] = 0;
    }
    __syncthreads();

    int b = blockIdx.x;
    unsigned char* myh = wb[wid];
    int lbase = lane << 2;

    float csum = 0.f;
    unsigned long long facc = 0ull, shacc = 0ull;
    int vpack = 0;

    // unroll 1: keeps only ONE tile's loads live at a time (register pressure)
    #pragma unroll 1
    for (int h = 0; h < 2; h++) {
        tileWork(b*BE1 + (h << 10) + t*4, n, lane, lp, st, q, fam, mic, vm, outStruct,
                 csum, vpack, 1 << (h << 4), facc, shacc, myh, lbase);
    }

    __syncwarp();
    // per-warp nibble-hist flush (2x16 split keeps per-byte partials <= 128)
    if (lane < 16) {
        const unsigned* wrow = (const unsigned*)wb[wid];
        int rbase = lane * 32;
        unsigned loA = 0u, hiA = 0u, loB = 0u, hiB = 0u;
        #pragma unroll
        for (int w = 0; w < 16; w++) {
            unsigned u = wrow[rbase + ((w + lane) & 31)];
            loA += u & 0x0F0F0F0Fu;
            hiA += (u >> 4) & 0x0F0F0F0Fu;
        }
        #pragma unroll
        for (int w = 16; w < 32; w++) {
            unsigned u = wrow[rbase + ((w + lane) & 31)];
            loB += u & 0x0F0F0F0Fu;
            hiB += (u >> 4) & 0x0F0F0F0Fu;
        }
        int off = (lane < 8) ? 0 : 64;
        int group = lane & 7;
        #pragma unroll
        for (int c = 0; c < 4; c++) {
            int lo = (int)((loA >> (8*c)) & 0xff) + (int)((loB >> (8*c)) & 0xff);
            int hi = (int)((hiA >> (8*c)) & 0xff) + (int)((hiB >> (8*c)) & 0xff);
            atomicAdd(&blkH[off + group*8 + c*2 + 0], lo);
            atomicAdd(&blkH[off + group*8 + c*2 + 1], hi);
        }
    }

    // deterministic per-block reductions (fixed order; csum path deterministic)
    #pragma unroll
    for (int o = 16; o; o >>= 1) {
        csum  += __shfl_down_sync(FULLM, csum,  o);
        vpack += __shfl_down_sync(FULLM, vpack, o);
        facc  += __shfl_down_sync(FULLM, facc,  o);
        shacc += __shfl_down_sync(FULLM, shacc, o);
    }
    if (lane == 0) {
        swC[wid] = csum; swV[wid] = vpack; swF[wid] = facc;
        #pragma unroll
        for (int f = 0; f < 7; f++) {
            int c = (int)((shacc >> (9*f)) & 511ull);
            if (c) atomicAdd(&sShell[f], c);
        }
    }
    __syncthreads();

    // global flush
    if (t < 128) {
        int c = blkH[t];
        if (c) atomicAdd((t < 64) ? &g_qh[t] : &g_mich[t - 64], c);
    }
    if (t < 7) {
        int c = sShell[t];
        if (c) atomicAdd(&g_shellh[t], c);
    }
    if (t == 0) {
        float cs = 0.f; int vp = 0; unsigned long long fs = 0ull;
        for (int w = 0; w < 8; w++) { cs += swC[w]; vp += swV[w]; fs += swF[w]; }
        g_blkC[b] = cs;
        g_blkV[2*b]     = vp & 0xffff;
        g_blkV[2*b + 1] = (vp >> 16) & 0xffff;
        atomicAdd(&g_famh[0], (int)( fs        & 0xffff));
        atomicAdd(&g_famh[1], (int)((fs >> 16) & 0xffff));
        atomicAdd(&g_famh[2], (int)((fs >> 32) & 0xffff));
        atomicAdd(&g_famh[3], (int)((fs >> 48) & 0xffff));
    }
}

// ---------------- K2: 1024 thr, shuffle vpfx scan (int4) + bit-identical csum tree ----------------
__global__ __launch_bounds__(1024) void k2(float* __restrict__ out, int n, int NB1, int NBV) {
    __shared__ int sScan[32];
    __shared__ float sf[1024];
    int t = threadIdx.x, lane = t & 31, wid = t >> 5;

    // (a) integer vpfx scan: 4 contiguous half-blocks per thread, int4 loads
    int4 v4;
    int bi0 = 4*t;
    if (bi0 + 3 < NBV) {
        v4 = *(const int4*)(g_blkV + bi0);
    } else {
        v4.x = (bi0+0 < NBV) ? g_blkV[bi0+0] : 0;
        v4.y = (bi0+1 < NBV) ? g_blkV[bi0+1] : 0;
        v4.z = (bi0+2 < NBV) ? g_blkV[bi0+2] : 0;
        v4.w = (bi0+3 < NBV) ? g_blkV[bi0+3] : 0;
    }
    int tsum = v4.x + v4.y + v4.z + v4.w;
    int incl = tsum;
    #pragma unroll
    for (int d = 1; d < 32; d <<= 1) {
        int o = __shfl_up_sync(FULLM, incl, d);
        if (lane >= d) incl += o;
    }
    if (lane == 31) sScan[wid] = incl;
    __syncthreads();
    if (wid == 0) {
        int x = sScan[lane];
        #pragma unroll
        for (int d = 1; d < 32; d <<= 1) {
            int o = __shfl_up_sync(FULLM, x, d);
            if (lane >= d) x += o;
        }
        sScan[lane] = x;   // inclusive scan of warp sums
    }
    __syncthreads();
    int woff = wid ? sScan[wid - 1] : 0;
    int run = woff + incl - tsum;
    if (bi0 + 3 < NBV) {
        int4 o4;
        o4.x = run; run += v4.x;
        o4.y = run; run += v4.y;
        o4.z = run; run += v4.z;
        o4.w = run;
        *(int4*)(g_vpfx + bi0) = o4;
    } else {
        if (bi0+0 < NBV) g_vpfx[bi0+0] = run; run += v4.x;
        if (bi0+1 < NBV) g_vpfx[bi0+1] = run; run += v4.y;
        if (bi0+2 < NBV) g_vpfx[bi0+2] = run; run += v4.z;
        if (bi0+3 < NBV) g_vpfx[bi0+3] = run;
    }
    int total = sScan[31];

    // (b) csum tree — BIT-IDENTICAL to the validated 1024-slot pairwise tree
    {
        int b0 = 2*t, b1 = 2*t + 1;
        float c2 = 0.f;
        if (b0 < NB1) c2 += g_blkC[b0];
        if (b1 < NB1) c2 += g_blkC[b1];
        sf[t] = c2;
    }
    __syncthreads();
    for (int d = 512; d; d >>= 1) { if (t < d) sf[t] += sf[t + d]; __syncthreads(); }

    if (t == 0) {
        g_totValid = total;
        float vcf = fmaxf((float)total, 1.0f);
        float cur = sf[0] / vcf;
        cur = fminf(fmaxf(cur, 1e-4f), 1.0f - 1e-4f);
        float tgt = 1.0f / 6.0f;  // 1 / TARGET_BPP (within clip range)
        float shift = (logf(tgt) - log1pf(-tgt)) - (logf(cur) - log1pf(-cur));
        g_E = expf(shift);
        g_cpT = (float)(1.0 / (1.0 + exp((double)shift)));   // sigmoid(-shift)
    }

    // (c) small-hist outputs (K1 fully done before K2 in stream order)
    float* H = out + 3 * (size_t)n;
    if (t < 64)              H[t] = (float)g_qh[t];
    if (t >= 64 && t < 68)   H[t] = (float)g_famh[t - 64];
    if (t >= 128 && t < 192) H[68 + (t - 128)] = (float)g_mich[t - 128];
    if (t >= 256 && t < 263) H[132 + (t - 256)] = (float)g_shellh[t - 256];
    if (t >= 288 && t < 295) {            // q_weight_hist7 from q hist
        int w = t - 288, acc2 = 0;
        for (int qq = 0; qq < 64; qq++) if (__popc(qq) == w) acc2 += g_qh[qq];
        H[139 + w] = (float)acc2;
    }
    if (t >= 320 && t < 326) {            // bit_excitation6 from q hist
        int j = t - 320, acc2 = 0;
        for (int qq = 0; qq < 64; qq++) acc2 += g_qh[qq] * ((qq >> j) & 1);
        H[146 + j] = (float)acc2;
    }
}

// ---------------- K3: combined logprobs, bmask, lengths (lean math) ----------------
__global__ __launch_bounds__(TPB) void k3(
    const int* __restrict__ vm,
    float* __restrict__ outCL, float* __restrict__ outBM, float* __restrict__ outLen,
    int n)
{
    __shared__ int swS[8], swM[8], swB[8];
    __shared__ int s_fi, s_fp;
    int t = threadIdx.x, b = blockIdx.x;
    int lane = t & 31, wid = t >> 5;
    if (t == 0) s_fi = INT_MAX;
    int i0 = b * BE3 + t * 4;
    float E   = g_E;
    float cpT = g_cpT;
    int vOff = g_vpfx[b];

    // valid bitmask for my 4 elements (valid_mask stored as int32)
    int4 vv = __ldg((const int4*)(vm + i0));
    unsigned vmask = 0;
    if (vv.x) vmask |= 1u;
    if (vv.y) vmask |= 2u;
    if (vv.z) vmask |= 4u;
    if (vv.w) vmask |= 8u;

    int tsum = __popc(vmask);
    int incl = tsum;
    #pragma unroll
    for (int d = 1; d < 32; d <<= 1) {
        int o = __shfl_up_sync(FULLM, incl, d);
        if (lane >= d) incl += o;
    }
    if (lane == 31) swS[wid] = incl;

    // lean math: sigmoid(logit(cp)+shift) == cp*E / (cp*E + 1-cp); bmask via cp >= cpT
    float4 c4 = __ldg((const float4*)(g_cp + i0));
    float ca[4] = { c4.x, c4.y, c4.z, c4.w };
    float clo[4], bmo[4];
    unsigned bvmask = 0;
    #pragma unroll
    for (int k = 0; k < 4; k++) {
        float cpc = fminf(fmaxf(ca[k], 1e-6f), 1.0f - 1e-6f);
        float a = cpc * E;
        float cb = __fdividef(a, a + (1.0f - cpc));
        cb = fminf(fmaxf(cb, 1e-6f), 1.0f - 1e-6f);
        clo[k] = __logf(cb);
        bool bm = (cpc >= cpT);          // exact monotone equivalent of cl >= log(0.5)
        bmo[k] = bm ? 1.0f : 0.0f;
        if (bm && ((vmask >> k) & 1)) bvmask |= 1u << k;
    }
    *(float4*)(outCL + i0) = make_float4(clo[0], clo[1], clo[2], clo[3]);
    *(float4*)(outBM + i0) = make_float4(bmo[0], bmo[1], bmo[2], bmo[3]);

    __syncthreads();   // S1: swS visible
    int blkE = 0;
    for (int w = 0; w < wid; w++) blkE += swS[w];
    int posExcl = vOff + blkE + (incl - tsum);

    // last boundary pos in my segment (pos is nondecreasing => max == last)
    int tlast = 0;
    if (bvmask) {
        int kb = 31 - __clz(bvmask);
        tlast = posExcl + __popc(vmask & ((2u << kb) - 1));
    }
    int im = tlast;
    #pragma unroll
    for (int d = 1; d < 32; d <<= 1) {
        int o = __shfl_up_sync(FULLM, im, d);
        if (lane >= d) im = max(im, o);
    }
    // shuffle executed unconditionally by ALL lanes; select afterwards
    int texm_raw = __shfl_up_sync(FULLM, im, 1);
    int texm = (lane == 0) ? 0 : texm_raw;
    if (lane == 31) swM[wid] = im;

    int bc = __popc(bvmask);
    #pragma unroll
    for (int o = 16; o; o >>= 1) bc += __shfl_down_sync(FULLM, bc, o);
    if (lane == 0) swB[wid] = bc;

    // per-thread first boundary (fixed up with cross-block carry in K4)
    int tfi = INT_MAX, tfp = 0;
    if (bvmask) {
        int kf = __ffs(bvmask) - 1;
        tfi = i0 + kf;
        tfp = posExcl + __popc(vmask & ((2u << kf) - 1));
    }
    atomicMin(&s_fi, tfi);

    __syncthreads();   // S2: swM, swB, s_fi visible
    int blkM = 0;
    for (int w = 0; w < wid; w++) blkM = max(blkM, swM[w]);
    int running = max(blkM, texm);   // exclusive prev (carry=0; first boundary fixed by K4)

    float lo[4];
    #pragma unroll
    for (int k = 0; k < 4; k++) {
        float lenv = 0.0f;
        if ((bvmask >> k) & 1) {
            int posk = posExcl + __popc(vmask & ((2u << k) - 1));
            lenv = (float)(posk - running);
            running = posk;
        }
        lo[k] = lenv;
    }
    // outLen base pointer is offset by 152 floats (not 16B aligned) -> scalar stores
    outLen[i0+0] = lo[0]; outLen[i0+1] = lo[1]; outLen[i0+2] = lo[2]; outLen[i0+3] = lo[3];

    if (tfi != INT_MAX && tfi == s_fi) s_fp = tfp;

    __syncthreads();   // S3
    if (t == 0) {
        int bl = 0, bcnt = 0;
        for (int w = 0; w < 8; w++) { bl = max(bl, swM[w]); bcnt += swB[w]; }
        g_blkLast[b]     = bl;
        g_blkBvCnt[b]    = bcnt;
        g_blkFirstIdx[b] = (s_fi == INT_MAX) ? -1 : s_fi;
        g_blkFirstPos[b] = (s_fi == INT_MAX) ? 0 : s_fp;
    }
}

// ---------------- K4: 1024 thr, 4/thread int4, shuffle max-scan + scalars + re-zero ----------------
__global__ __launch_bounds__(1024) void k4(float* __restrict__ out, int n, int NBV) {
    __shared__ int sw[32], sb[32];
    int t = threadIdx.x, lane = t & 31, wid = t >> 5;

    int bi0 = 4*t;
    int4 l4, b4;
    if (bi0 + 3 < NBV) {
        l4 = *(const int4*)(g_blkLast  + bi0);
        b4 = *(const int4*)(g_blkBvCnt + bi0);
    } else {
        l4.x = (bi0+0 < NBV) ? g_blkLast[bi0+0] : 0;
        l4.y = (bi0+1 < NBV) ? g_blkLast[bi0+1] : 0;
        l4.z = (bi0+2 < NBV) ? g_blkLast[bi0+2] : 0;
        l4.w = (bi0+3 < NBV) ? g_blkLast[bi0+3] : 0;
        b4.x = (bi0+0 < NBV) ? g_blkBvCnt[bi0+0] : 0;
        b4.y = (bi0+1 < NBV) ? g_blkBvCnt[bi0+1] : 0;
        b4.z = (bi0+2 < NBV) ? g_blkBvCnt[bi0+2] : 0;
        b4.w = (bi0+3 < NBV) ? g_blkBvCnt[bi0+3] : 0;
    }
    int bsum = b4.x + b4.y + b4.z + b4.w;
    int m[4];
    int runM = l4.x;         m[0] = runM;
    runM = max(runM, l4.y);  m[1] = runM;
    runM = max(runM, l4.z);  m[2] = runM;
    runM = max(runM, l4.w);  m[3] = runM;

    int inclM = runM;
    #pragma unroll
    for (int d = 1; d < 32; d <<= 1) {
        int o = __shfl_up_sync(FULLM, inclM, d);
        if (lane >= d) inclM = max(inclM, o);
    }
    if (lane == 31) sw[wid] = inclM;
    int bs = bsum;
    #pragma unroll
    for (int o = 16; o; o >>= 1) bs += __shfl_down_sync(FULLM, bs, o);
    if (lane == 0) sb[wid] = bs;
    __syncthreads();

    if (wid == 0) {
        int x = sw[lane];
        #pragma unroll
        for (int d = 1; d < 32; d <<= 1) {
            int o = __shfl_up_sync(FULLM, x, d);
            if (lane >= d) x = max(x, o);
        }
        sw[lane] = x;                       // inclusive max-scan of warp maxima
        int y = sb[lane];
        #pragma unroll
        for (int o = 16; o; o >>= 1) y += __shfl_down_sync(FULLM, y, o);
        if (lane == 0) sb[0] = y;           // total boundary count
    }
    __syncthreads();

    int wprev = wid ? sw[wid - 1] : 0;
    int lprev_raw = __shfl_up_sync(FULLM, inclM, 1);
    int lprev = lane ? lprev_raw : 0;
    int Ex = max(wprev, lprev);             // exclusive max before this thread's 4 blocks

    int4 fi4, fp4;
    if (bi0 + 3 < NBV) {
        fi4 = *(const int4*)(g_blkFirstIdx + bi0);
        fp4 = *(const int4*)(g_blkFirstPos + bi0);
    } else {
        fi4.x = (bi0+0 < NBV) ? g_blkFirstIdx[bi0+0] : -1;
        fi4.y = (bi0+1 < NBV) ? g_blkFirstIdx[bi0+1] : -1;
        fi4.z = (bi0+2 < NBV) ? g_blkFirstIdx[bi0+2] : -1;
        fi4.w = (bi0+3 < NBV) ? g_blkFirstIdx[bi0+3] : -1;
        fp4.x = (bi0+0 < NBV) ? g_blkFirstPos[bi0+0] : 0;
        fp4.y = (bi0+1 < NBV) ? g_blkFirstPos[bi0+1] : 0;
        fp4.z = (bi0+2 < NBV) ? g_blkFirstPos[bi0+2] : 0;
        fp4.w = (bi0+3 < NBV) ? g_blkFirstPos[bi0+3] : 0;
    }
    int fia[4] = { fi4.x, fi4.y, fi4.z, fi4.w };
    int fpa[4] = { fp4.x, fp4.y, fp4.z, fp4.w };
    #pragma unroll
    for (int j = 0; j < 4; j++) {
        if (fia[j] >= 0) {
            int ex = (j > 0) ? max(Ex, m[j-1]) : Ex;
            out[3 * (size_t)n + 152 + fia[j]] = (float)(fpa[j] - ex);
        }
    }

    if (t == 0) {
        int globalLast = sw[31];
        int tv = g_totValid;
        int trailing = tv - globalLast;
        int pc = sb[0] + (trailing > 0 ? 1 : 0);
        out[4 * (size_t)n + 152] = (float)trailing;
        out[4 * (size_t)n + 153] = (float)pc;
    }

    // re-zero global hist accumulators for the next replay of this graph
    // (module load starts them zeroed; every call restores the invariant)
    if (t < 64) { g_qh[t] = 0; g_mich[t] = 0; }
    if (t < 7)  g_shellh[t] = 0;
    if (t < 4)  g_famh[t] = 0;
}

// ---------------- launch ----------------
extern "C" void kernel_launch(void* const* d_in, const int* in_sizes, int n_in,
                              void* d_out, int out_size) {
    const float* lp = (const float*)d_in[0];
    const int* st   = (const int*)d_in[1];
    const int* q    = (const int*)d_in[2];
    const int* fam  = (const int*)d_in[3];
    const int* mic  = (const int*)d_in[4];
    const int* vm   = (const int*)d_in[5];   // bool promoted to int32 by harness
    float* out = (float*)d_out;
    int n = in_sizes[0];            // 4194304
    int NB1 = (n + BE1 - 1) / BE1;  // 2048 k1 blocks
    int NBV = NB1 * 2;              // 4096 half-blocks (= k3 blocks)

    k1<<<NB1, TPB>>>(lp, st, q, fam, mic, vm, out + 2 * (size_t)n, n);
    k2<<<1, 1024>>>(out, n, NB1, NBV);
    k3<<<NBV, TPB>>>(vm, out, out + (size_t)n, out + 3 * (size_t)n + 152, n);
    k4<<<1, 1024>>>(out, n, NBV);
}

// round 15
// speedup vs baseline: 1.1960x; 1.0385x over previous
#include <cuda_runtime.h>
#include <stdint.h>
#include <limits.h>

#define TPB 256
#define BE1 2048          // elements per k1 block (two 1024-halves)
#define BE3 1024          // elements per k3 block
#define NBMAX 4096
#define NMAX  4194304
#define FULLM 0xffffffffu

// ---------------- device scratch (no allocations allowed) ----------------
__device__ float g_cp[NMAX];      // combined prob (pre-shift), written by k1, read by k3
__device__ int   g_qh[64];
__device__ int   g_mich[64];
__device__ int   g_shellh[7];
__device__ int   g_famh[4];
__device__ int   g_blkV[NBMAX];   // valid count per 1024-element half-block
__device__ float g_blkC[NBMAX];   // csum per k1 block (2048 elems)
__device__ int   g_vpfx[NBMAX];   // exclusive valid prefix per 1024-element half-block
__device__ int   g_blkLast[NBMAX];
__device__ int   g_blkFirstIdx[NBMAX];
__device__ int   g_blkFirstPos[NBMAX];
__device__ int   g_blkBvCnt[NBMAX];
__device__ float g_E;             // exp(shift)
__device__ float g_cpT;           // sigmoid(-shift): bmask <=> cp >= g_cpT
__device__ int   g_totValid;

// ---------------- K1 tile worker (1 float4/int4 tile, fully coalesced) ----------------
__device__ __forceinline__ void tileWork(
    int i0, int n, int lane,
    const float* __restrict__ lp, const int* __restrict__ st,
    const int* __restrict__ q,  const int* __restrict__ fam,
    const int* __restrict__ mic, const int* __restrict__ vm,
    float* __restrict__ outStruct,
    float& csum, int& vpack, int vinc,
    unsigned long long& facc, unsigned long long& shacc,
    unsigned char* myh, int lbase)
{
    int4   s4 = __ldg((const int4*)(st  + i0));
    int4   q4 = __ldg((const int4*)(q   + i0));
    int4   f4 = __ldg((const int4*)(fam + i0));
    int4   m4 = __ldg((const int4*)(mic + i0));
    float4 l4 = __ldg((const float4*)(lp + i0));
    int4   v4 = __ldg((const int4*)(vm  + i0));

    // neighbor (element i0+4) via warp shuffle; lane 31 loads from global
    int sn = __shfl_down_sync(FULLM, s4.x, 1);
    int qn = __shfl_down_sync(FULLM, q4.x, 1);
    int fn = __shfl_down_sync(FULLM, f4.x, 1);
    int nsi = i0 + 4;
    if (lane == 31) {
        bool inr = (nsi < n);
        sn = inr ? __ldg(st  + nsi) : 0;
        qn = inr ? __ldg(q   + nsi) : 0;
        fn = inr ? __ldg(fam + nsi) : 0;
    }

    int   sa[5] = { s4.x, s4.y, s4.z, s4.w, sn };
    int   qa[5] = { q4.x, q4.y, q4.z, q4.w, qn };
    int   fa[5] = { f4.x, f4.y, f4.z, f4.w, fn };
    int   ma[4] = { m4.x, m4.y, m4.z, m4.w };
    float la[4] = { l4.x, l4.y, l4.z, l4.w };
    int   va[4] = { v4.x, v4.y, v4.z, v4.w };

    float so[4], cpo[4];
    #pragma unroll
    for (int k = 0; k < 4; k++) {
        int c6  = ((sa[k]   >> 6) ^ sa[k]  ) & 63;
        int c6n = ((sa[k+1] >> 6) ^ sa[k+1]) & 63;
        float d_chi = (float)__popc(c6 ^ c6n) / 6.0f;
        float d_q   = (float)__popc((qa[k] & 63) ^ (qa[k+1] & 63)) / 6.0f;
        float d_f   = (float)__popc((fa[k] ^ fa[k+1]) & 3) * 0.5f;
        float score = 0.5f*d_chi + 0.35f*d_q + 0.15f*d_f;
        score = fminf(fmaxf(score, 1e-6f), 1.0f);
        bool v = (va[k] != 0);
        so[k] = v ? score : 0.0f;
        float cosine = expf(fminf(la[k], 0.0f));   // accurate expf: feeds threshold path
        float cpv = 0.5f*cosine + 0.5f*so[k];
        cpo[k] = cpv;
        if (v) {
            csum += cpv;
            vpack += vinc;
            int qb = qa[k] & 63;
            int aq = ((qb >> 3) << 7) + lbase + ((qb >> 1) & 3);
            myh[aq] = (unsigned char)(myh[aq] + (1 << ((qb & 1) << 2)));
            int mb = ma[k] & 63;
            int am = 1024 + ((mb >> 3) << 7) + lbase + ((mb >> 1) & 3);
            myh[am] = (unsigned char)(myh[am] + (1 << ((mb & 1) << 2)));
            facc  += 1ull << ((fa[k] & 3) << 4);
            shacc += 1ull << (__popc(c6) * 9);
        }
    }
    *(float4*)(outStruct + i0) = make_float4(so[0], so[1], so[2], so[3]);
    *(float4*)(g_cp + i0)      = make_float4(cpo[0], cpo[1], cpo[2], cpo[3]);
}

// ---------------- K1: structural + cp + atomic-free histograms (2 tiles/thread) ----------------
__global__ __launch_bounds__(TPB, 5) void k1(
    const float* __restrict__ lp, const int* __restrict__ st,
    const int* __restrict__ q,  const int* __restrict__ fam,
    const int* __restrict__ mic, const int* __restrict__ vm,
    float* __restrict__ outStruct, int n)
{
    __shared__ unsigned char wb[8][2048];
    __shared__ int blkH[128];
    __shared__ int sShell[7];
    __shared__ float swC[8];
    __shared__ int   swV[8];
    __shared__ unsigned long long swF[8];

    int t = threadIdx.x, lane = t & 31, wid = t >> 5;
    {   // zero 16KB of nibble counters + small arrays
        unsigned* w32 = (unsigned*)wb;
        #pragma unroll
        for (int i = 0; i < 16; i++) w32[t + i*TPB] = 0u;
        if (t < 128) blkH[t] = 0;
        if (t < 7)   sShell[t] = 0;
    }
    __syncthreads();

    int b = blockIdx.x;
    unsigned char* myh = wb[wid];
    int lbase = lane << 2;

    float csum = 0.f;
    unsigned long long facc = 0ull, shacc = 0ull;
    int vpack = 0;

    // unroll 1: keeps only ONE tile's loads live at a time (register pressure)
    #pragma unroll 1
    for (int h = 0; h < 2; h++) {
        tileWork(b*BE1 + (h << 10) + t*4, n, lane, lp, st, q, fam, mic, vm, outStruct,
                 csum, vpack, 1 << (h << 4), facc, shacc, myh, lbase);
    }

    __syncwarp();
    // per-warp nibble-hist flush (2x16 split keeps per-byte partials <= 128)
    if (lane < 16) {
        const unsigned* wrow = (const unsigned*)wb[wid];
        int rbase = lane * 32;
        unsigned loA = 0u, hiA = 0u, loB = 0u, hiB = 0u;
        #pragma unroll
        for (int w = 0; w < 16; w++) {
            unsigned u = wrow[rbase + ((w + lane) & 31)];
            loA += u & 0x0F0F0F0Fu;
            hiA += (u >> 4) & 0x0F0F0F0Fu;
        }
        #pragma unroll
        for (int w = 16; w < 32; w++) {
            unsigned u = wrow[rbase + ((w + lane) & 31)];
            loB += u & 0x0F0F0F0Fu;
            hiB += (u >> 4) & 0x0F0F0F0Fu;
        }
        int off = (lane < 8) ? 0 : 64;
        int group = lane & 7;
        #pragma unroll
        for (int c = 0; c < 4; c++) {
            int lo = (int)((loA >> (8*c)) & 0xff) + (int)((loB >> (8*c)) & 0xff);
            int hi = (int)((hiA >> (8*c)) & 0xff) + (int)((hiB >> (8*c)) & 0xff);
            atomicAdd(&blkH[off + group*8 + c*2 + 0], lo);
            atomicAdd(&blkH[off + group*8 + c*2 + 1], hi);
        }
    }

    // deterministic per-block reductions (fixed order; csum path deterministic)
    #pragma unroll
    for (int o = 16; o; o >>= 1) {
        csum  += __shfl_down_sync(FULLM, csum,  o);
        vpack += __shfl_down_sync(FULLM, vpack, o);
        facc  += __shfl_down_sync(FULLM, facc,  o);
        shacc += __shfl_down_sync(FULLM, shacc, o);
    }
    if (lane == 0) {
        swC[wid] = csum; swV[wid] = vpack; swF[wid] = facc;
        #pragma unroll
        for (int f = 0; f < 7; f++) {
            int c = (int)((shacc >> (9*f)) & 511ull);
            if (c) atomicAdd(&sShell[f], c);
        }
    }
    __syncthreads();

    // global flush
    if (t < 128) {
        int c = blkH[t];
        if (c) atomicAdd((t < 64) ? &g_qh[t] : &g_mich[t - 64], c);
    }
    if (t < 7) {
        int c = sShell[t];
        if (c) atomicAdd(&g_shellh[t], c);
    }
    if (t == 0) {
        float cs = 0.f; int vp = 0; unsigned long long fs = 0ull;
        for (int w = 0; w < 8; w++) { cs += swC[w]; vp += swV[w]; fs += swF[w]; }
        g_blkC[b] = cs;
        g_blkV[2*b]     = vp & 0xffff;
        g_blkV[2*b + 1] = (vp >> 16) & 0xffff;
        atomicAdd(&g_famh[0], (int)( fs        & 0xffff));
        atomicAdd(&g_famh[1], (int)((fs >> 16) & 0xffff));
        atomicAdd(&g_famh[2], (int)((fs >> 32) & 0xffff));
        atomicAdd(&g_famh[3], (int)((fs >> 48) & 0xffff));
    }
    cudaTriggerProgrammaticLaunchCompletion();
}

// ---------------- K2: 1024 thr, shuffle vpfx scan (int4) + bit-identical csum tree ----------------
__global__ __launch_bounds__(1024) void k2(float* __restrict__ out, int n, int NB1, int NBV) {
    __shared__ int sScan[32];
    __shared__ float sf[1024];
    int t = threadIdx.x, lane = t & 31, wid = t >> 5;

    cudaGridDependencySynchronize();   // wait for k1's writes (PDL)

    // (a) integer vpfx scan: 4 contiguous half-blocks per thread, int4 loads
    int4 v4;
    int bi0 = 4*t;
    if (bi0 + 3 < NBV) {
        v4 = *(const int4*)(g_blkV + bi0);
    } else {
        v4.x = (bi0+0 < NBV) ? g_blkV[bi0+0] : 0;
        v4.y = (bi0+1 < NBV) ? g_blkV[bi0+1] : 0;
        v4.z = (bi0+2 < NBV) ? g_blkV[bi0+2] : 0;
        v4.w = (bi0+3 < NBV) ? g_blkV[bi0+3] : 0;
    }
    int tsum = v4.x + v4.y + v4.z + v4.w;
    int incl = tsum;
    #pragma unroll
    for (int d = 1; d < 32; d <<= 1) {
        int o = __shfl_up_sync(FULLM, incl, d);
        if (lane >= d) incl += o;
    }
    if (lane == 31) sScan[wid] = incl;
    __syncthreads();
    if (wid == 0) {
        int x = sScan[lane];
        #pragma unroll
        for (int d = 1; d < 32; d <<= 1) {
            int o = __shfl_up_sync(FULLM, x, d);
            if (lane >= d) x += o;
        }
        sScan[lane] = x;   // inclusive scan of warp sums
    }
    __syncthreads();
    int woff = wid ? sScan[wid - 1] : 0;
    int run = woff + incl - tsum;
    if (bi0 + 3 < NBV) {
        int4 o4;
        o4.x = run; run += v4.x;
        o4.y = run; run += v4.y;
        o4.z = run; run += v4.z;
        o4.w = run;
        *(int4*)(g_vpfx + bi0) = o4;
    } else {
        if (bi0+0 < NBV) g_vpfx[bi0+0] = run; run += v4.x;
        if (bi0+1 < NBV) g_vpfx[bi0+1] = run; run += v4.y;
        if (bi0+2 < NBV) g_vpfx[bi0+2] = run; run += v4.z;
        if (bi0+3 < NBV) g_vpfx[bi0+3] = run;
    }
    int total = sScan[31];

    // (b) csum tree — BIT-IDENTICAL to the validated 1024-slot pairwise tree
    {
        int b0 = 2*t, b1 = 2*t + 1;
        float c2 = 0.f;
        if (b0 < NB1) c2 += g_blkC[b0];
        if (b1 < NB1) c2 += g_blkC[b1];
        sf[t] = c2;
    }
    __syncthreads();
    for (int d = 512; d; d >>= 1) { if (t < d) sf[t] += sf[t + d]; __syncthreads(); }

    if (t == 0) {
        g_totValid = total;
        float vcf = fmaxf((float)total, 1.0f);
        float cur = sf[0] / vcf;
        cur = fminf(fmaxf(cur, 1e-4f), 1.0f - 1e-4f);
        float tgt = 1.0f / 6.0f;  // 1 / TARGET_BPP (within clip range)
        float shift = (logf(tgt) - log1pf(-tgt)) - (logf(cur) - log1pf(-cur));
        g_E = expf(shift);
        g_cpT = (float)(1.0 / (1.0 + exp((double)shift)));   // sigmoid(-shift)
    }

    // (c) small-hist outputs (K1 fully done per gridsync)
    float* H = out + 3 * (size_t)n;
    if (t < 64)              H[t] = (float)g_qh[t];
    if (t >= 64 && t < 68)   H[t] = (float)g_famh[t - 64];
    if (t >= 128 && t < 192) H[68 + (t - 128)] = (float)g_mich[t - 128];
    if (t >= 256 && t < 263) H[132 + (t - 256)] = (float)g_shellh[t - 256];
    if (t >= 288 && t < 295) {            // q_weight_hist7 from q hist
        int w = t - 288, acc2 = 0;
        for (int qq = 0; qq < 64; qq++) if (__popc(qq) == w) acc2 += g_qh[qq];
        H[139 + w] = (float)acc2;
    }
    if (t >= 320 && t < 326) {            // bit_excitation6 from q hist
        int j = t - 320, acc2 = 0;
        for (int qq = 0; qq < 64; qq++) acc2 += g_qh[qq] * ((qq >> j) & 1);
        H[146 + j] = (float)acc2;
    }
    cudaTriggerProgrammaticLaunchCompletion();
}

// ---------------- K3: combined logprobs, bmask, lengths (lean math, PDL prefetch) ----------------
__global__ __launch_bounds__(TPB) void k3(
    const int* __restrict__ vm,
    float* __restrict__ outCL, float* __restrict__ outBM, float* __restrict__ outLen,
    int n)
{
    __shared__ int swS[8], swM[8], swB[8];
    __shared__ int s_fi, s_fp;
    int t = threadIdx.x, b = blockIdx.x;
    int lane = t & 31, wid = t >> 5;
    if (t == 0) s_fi = INT_MAX;
    int i0 = b * BE3 + t * 4;

    // ---- pre-sync phase: everything independent of k2 ----
    // (vm is harness input; g_cp was written by k1, complete before k2's trigger)
    int4 vv = __ldg((const int4*)(vm + i0));
    unsigned vmask = 0;
    if (vv.x) vmask |= 1u;
    if (vv.y) vmask |= 2u;
    if (vv.z) vmask |= 4u;
    if (vv.w) vmask |= 8u;

    int tsum = __popc(vmask);
    int incl = tsum;
    #pragma unroll
    for (int d = 1; d < 32; d <<= 1) {
        int o = __shfl_up_sync(FULLM, incl, d);
        if (lane >= d) incl += o;
    }
    if (lane == 31) swS[wid] = incl;

    float4 c4 = __ldg((const float4*)(g_cp + i0));

    cudaGridDependencySynchronize();   // wait for k2's g_E/g_cpT/g_vpfx (PDL)
    float E   = g_E;
    float cpT = g_cpT;
    int vOff = g_vpfx[b];

    // lean math: sigmoid(logit(cp)+shift) == cp*E / (cp*E + 1-cp); bmask via cp >= cpT
    float ca[4] = { c4.x, c4.y, c4.z, c4.w };
    float clo[4], bmo[4];
    unsigned bvmask = 0;
    #pragma unroll
    for (int k = 0; k < 4; k++) {
        float cpc = fminf(fmaxf(ca[k], 1e-6f), 1.0f - 1e-6f);
        float a = cpc * E;
        float cb = __fdividef(a, a + (1.0f - cpc));
        cb = fminf(fmaxf(cb, 1e-6f), 1.0f - 1e-6f);
        clo[k] = __logf(cb);
        bool bm = (cpc >= cpT);          // exact monotone equivalent of cl >= log(0.5)
        bmo[k] = bm ? 1.0f : 0.0f;
        if (bm && ((vmask >> k) & 1)) bvmask |= 1u << k;
    }
    *(float4*)(outCL + i0) = make_float4(clo[0], clo[1], clo[2], clo[3]);
    *(float4*)(outBM + i0) = make_float4(bmo[0], bmo[1], bmo[2], bmo[3]);

    __syncthreads();   // S1: swS visible
    int blkE = 0;
    for (int w = 0; w < wid; w++) blkE += swS[w];
    int posExcl = vOff + blkE + (incl - tsum);

    // last boundary pos in my segment (pos is nondecreasing => max == last)
    int tlast = 0;
    if (bvmask) {
        int kb = 31 - __clz(bvmask);
        tlast = posExcl + __popc(vmask & ((2u << kb) - 1));
    }
    int im = tlast;
    #pragma unroll
    for (int d = 1; d < 32; d <<= 1) {
        int o = __shfl_up_sync(FULLM, im, d);
        if (lane >= d) im = max(im, o);
    }
    // shuffle executed unconditionally by ALL lanes; select afterwards
    int texm_raw = __shfl_up_sync(FULLM, im, 1);
    int texm = (lane == 0) ? 0 : texm_raw;
    if (lane == 31) swM[wid] = im;

    int bc = __popc(bvmask);
    #pragma unroll
    for (int o = 16; o; o >>= 1) bc += __shfl_down_sync(FULLM, bc, o);
    if (lane == 0) swB[wid] = bc;

    // per-thread first boundary (fixed up with cross-block carry in K4)
    int tfi = INT_MAX, tfp = 0;
    if (bvmask) {
        int kf = __ffs(bvmask) - 1;
        tfi = i0 + kf;
        tfp = posExcl + __popc(vmask & ((2u << kf) - 1));
    }
    atomicMin(&s_fi, tfi);

    __syncthreads();   // S2: swM, swB, s_fi visible
    int blkM = 0;
    for (int w = 0; w < wid; w++) blkM = max(blkM, swM[w]);
    int running = max(blkM, texm);   // exclusive prev (carry=0; first boundary fixed by K4)

    float lo[4];
    #pragma unroll
    for (int k = 0; k < 4; k++) {
        float lenv = 0.0f;
        if ((bvmask >> k) & 1) {
            int posk = posExcl + __popc(vmask & ((2u << k) - 1));
            lenv = (float)(posk - running);
            running = posk;
        }
        lo[k] = lenv;
    }
    // outLen base pointer is offset by 152 floats (not 16B aligned) -> scalar stores
    outLen[i0+0] = lo[0]; outLen[i0+1] = lo[1]; outLen[i0+2] = lo[2]; outLen[i0+3] = lo[3];

    if (tfi != INT_MAX && tfi == s_fi) s_fp = tfp;

    __syncthreads();   // S3
    if (t == 0) {
        int bl = 0, bcnt = 0;
        for (int w = 0; w < 8; w++) { bl = max(bl, swM[w]); bcnt += swB[w]; }
        g_blkLast[b]     = bl;
        g_blkBvCnt[b]    = bcnt;
        g_blkFirstIdx[b] = (s_fi == INT_MAX) ? -1 : s_fi;
        g_blkFirstPos[b] = (s_fi == INT_MAX) ? 0 : s_fp;
    }
    cudaTriggerProgrammaticLaunchCompletion();
}

// ---------------- K4: 1024 thr, 4/thread int4, shuffle max-scan + scalars + re-zero ----------------
__global__ __launch_bounds__(1024) void k4(float* __restrict__ out, int n, int NBV) {
    __shared__ int sw[32], sb[32];
    int t = threadIdx.x, lane = t & 31, wid = t >> 5;

    cudaGridDependencySynchronize();   // wait for k3's per-block arrays (PDL)

    int bi0 = 4*t;
    int4 l4, b4;
    if (bi0 + 3 < NBV) {
        l4 = *(const int4*)(g_blkLast  + bi0);
        b4 = *(const int4*)(g_blkBvCnt + bi0);
    } else {
        l4.x = (bi0+0 < NBV) ? g_blkLast[bi0+0] : 0;
        l4.y = (bi0+1 < NBV) ? g_blkLast[bi0+1] : 0;
        l4.z = (bi0+2 < NBV) ? g_blkLast[bi0+2] : 0;
        l4.w = (bi0+3 < NBV) ? g_blkLast[bi0+3] : 0;
        b4.x = (bi0+0 < NBV) ? g_blkBvCnt[bi0+0] : 0;
        b4.y = (bi0+1 < NBV) ? g_blkBvCnt[bi0+1] : 0;
        b4.z = (bi0+2 < NBV) ? g_blkBvCnt[bi0+2] : 0;
        b4.w = (bi0+3 < NBV) ? g_blkBvCnt[bi0+3] : 0;
    }
    int bsum = b4.x + b4.y + b4.z + b4.w;
    int m[4];
    int runM = l4.x;         m[0] = runM;
    runM = max(runM, l4.y);  m[1] = runM;
    runM = max(runM, l4.z);  m[2] = runM;
    runM = max(runM, l4.w);  m[3] = runM;

    int inclM = runM;
    #pragma unroll
    for (int d = 1; d < 32; d <<= 1) {
        int o = __shfl_up_sync(FULLM, inclM, d);
        if (lane >= d) inclM = max(inclM, o);
    }
    if (lane == 31) sw[wid] = inclM;
    int bs = bsum;
    #pragma unroll
    for (int o = 16; o; o >>= 1) bs += __shfl_down_sync(FULLM, bs, o);
    if (lane == 0) sb[wid] = bs;
    __syncthreads();

    if (wid == 0) {
        int x = sw[lane];
        #pragma unroll
        for (int d = 1; d < 32; d <<= 1) {
            int o = __shfl_up_sync(FULLM, x, d);
            if (lane >= d) x = max(x, o);
        }
        sw[lane] = x;                       // inclusive max-scan of warp maxima
        int y = sb[lane];
        #pragma unroll
        for (int o = 16; o; o >>= 1) y += __shfl_down_sync(FULLM, y, o);
        if (lane == 0) sb[0] = y;           // total boundary count
    }
    __syncthreads();

    int wprev = wid ? sw[wid - 1] : 0;
    int lprev_raw = __shfl_up_sync(FULLM, inclM, 1);
    int lprev = lane ? lprev_raw : 0;
    int Ex = max(wprev, lprev);             // exclusive max before this thread's 4 blocks

    int4 fi4, fp4;
    if (bi0 + 3 < NBV) {
        fi4 = *(const int4*)(g_blkFirstIdx + bi0);
        fp4 = *(const int4*)(g_blkFirstPos + bi0);
    } else {
        fi4.x = (bi0+0 < NBV) ? g_blkFirstIdx[bi0+0] : -1;
        fi4.y = (bi0+1 < NBV) ? g_blkFirstIdx[bi0+1] : -1;
        fi4.z = (bi0+2 < NBV) ? g_blkFirstIdx[bi0+2] : -1;
        fi4.w = (bi0+3 < NBV) ? g_blkFirstIdx[bi0+3] : -1;
        fp4.x = (bi0+0 < NBV) ? g_blkFirstPos[bi0+0] : 0;
        fp4.y = (bi0+1 < NBV) ? g_blkFirstPos[bi0+1] : 0;
        fp4.z = (bi0+2 < NBV) ? g_blkFirstPos[bi0+2] : 0;
        fp4.w = (bi0+3 < NBV) ? g_blkFirstPos[bi0+3] : 0;
    }
    int fia[4] = { fi4.x, fi4.y, fi4.z, fi4.w };
    int fpa[4] = { fp4.x, fp4.y, fp4.z, fp4.w };
    #pragma unroll
    for (int j = 0; j < 4; j++) {
        if (fia[j] >= 0) {
            int ex = (j > 0) ? max(Ex, m[j-1]) : Ex;
            out[3 * (size_t)n + 152 + fia[j]] = (float)(fpa[j] - ex);
        }
    }

    if (t == 0) {
        int globalLast = sw[31];
        int tv = g_totValid;
        int trailing = tv - globalLast;
        int pc = sb[0] + (trailing > 0 ? 1 : 0);
        out[4 * (size_t)n + 152] = (float)trailing;
        out[4 * (size_t)n + 153] = (float)pc;
    }

    // re-zero global hist accumulators for the next replay of this graph
    // (module load starts them zeroed; every call restores the invariant)
    if (t < 64) { g_qh[t] = 0; g_mich[t] = 0; }
    if (t < 7)  g_shellh[t] = 0;
    if (t < 4)  g_famh[t] = 0;
}

// ---------------- launch ----------------
extern "C" void kernel_launch(void* const* d_in, const int* in_sizes, int n_in,
                              void* d_out, int out_size) {
    const float* lp = (const float*)d_in[0];
    const int* st   = (const int*)d_in[1];
    const int* q    = (const int*)d_in[2];
    const int* fam  = (const int*)d_in[3];
    const int* mic  = (const int*)d_in[4];
    const int* vm   = (const int*)d_in[5];   // bool promoted to int32 by harness
    float* out = (float*)d_out;
    int n = in_sizes[0];            // 4194304
    int NB1 = (n + BE1 - 1) / BE1;  // 2048 k1 blocks
    int NBV = NB1 * 2;              // 4096 half-blocks (= k3 blocks)

    float* outStruct = out + 2 * (size_t)n;
    float* outBM     = out + (size_t)n;
    float* outLen    = out + 3 * (size_t)n + 152;

    cudaLaunchAttribute pdl[1];
    pdl[0].id = cudaLaunchAttributeProgrammaticStreamSerialization;
    pdl[0].val.programmaticStreamSerializationAllowed = 1;

    k1<<<NB1, TPB>>>(lp, st, q, fam, mic, vm, outStruct, n);

    {   // k2 with PDL
        cudaLaunchConfig_t cfg = {};
        cfg.gridDim = dim3(1); cfg.blockDim = dim3(1024);
        cfg.attrs = pdl; cfg.numAttrs = 1;
        cudaLaunchKernelEx(&cfg, k2, out, n, NB1, NBV);
    }
    {   // k3 with PDL
        cudaLaunchConfig_t cfg = {};
        cfg.gridDim = dim3(NBV); cfg.blockDim = dim3(TPB);
        cfg.attrs = pdl; cfg.numAttrs = 1;
        cudaLaunchKernelEx(&cfg, k3, vm, out, outBM, outLen, n);
    }
    {   // k4 with PDL
        cudaLaunchConfig_t cfg = {};
        cfg.gridDim = dim3(1); cfg.blockDim = dim3(1024);
        cfg.attrs = pdl; cfg.numAttrs = 1;
        cudaLaunchKernelEx(&cfg, k4, out, n, NBV);
    }
}

// round 17
// speedup vs baseline: 1.2012x; 1.0043x over previous
#include <cuda_runtime.h>
#include <stdint.h>
#include <limits.h>

#define TPB 256
#define BE1 2048          // elements per k1 block (two 1024-halves)
#define BE3 1024          // elements per k3 block
#define NBMAX 4096
#define NMAX  4194304
#define FULLM 0xffffffffu

// ---------------- device scratch (no allocations allowed) ----------------
__device__ float g_cp[NMAX];      // combined prob (pre-shift), written by k1, read by k3
__device__ unsigned char g_vb[NMAX/4];  // packed valid nibble per 4 elements (k1 -> k3)
__device__ int   g_qh[64];
__device__ int   g_mich[64];
__device__ int   g_shellh[7];
__device__ int   g_famh[4];
__device__ int   g_blkV[NBMAX];   // valid count per 1024-element half-block
__device__ float g_blkC[NBMAX];   // csum per k1 block (2048 elems)
__device__ int   g_vpfx[NBMAX];   // exclusive valid prefix per 1024-element half-block
__device__ int   g_blkLast[NBMAX];
__device__ int   g_blkFirstIdx[NBMAX];
__device__ int   g_blkFirstPos[NBMAX];
__device__ int   g_blkBvCnt[NBMAX];
__device__ float g_E;             // exp(shift)
__device__ float g_cpT;           // sigmoid(-shift): bmask <=> cp >= g_cpT
__device__ int   g_totValid;

// ---------------- K1 tile worker (1 float4/int4 tile, fully coalesced) ----------------
__device__ __forceinline__ void tileWork(
    int i0, int n, int lane,
    const float* __restrict__ lp, const int* __restrict__ st,
    const int* __restrict__ q,  const int* __restrict__ fam,
    const int* __restrict__ mic, const int* __restrict__ vm,
    float* __restrict__ outStruct,
    float& csum, int& vpack, int vinc,
    unsigned long long& facc, unsigned long long& shacc,
    unsigned char* myh, int lbase)
{
    int4   s4 = __ldg((const int4*)(st  + i0));
    int4   q4 = __ldg((const int4*)(q   + i0));
    int4   f4 = __ldg((const int4*)(fam + i0));
    int4   m4 = __ldg((const int4*)(mic + i0));
    float4 l4 = __ldg((const float4*)(lp + i0));
    int4   v4 = __ldg((const int4*)(vm  + i0));

    // neighbor (element i0+4) via warp shuffle; lane 31 loads from global
    int sn = __shfl_down_sync(FULLM, s4.x, 1);
    int qn = __shfl_down_sync(FULLM, q4.x, 1);
    int fn = __shfl_down_sync(FULLM, f4.x, 1);
    int nsi = i0 + 4;
    if (lane == 31) {
        bool inr = (nsi < n);
        sn = inr ? __ldg(st  + nsi) : 0;
        qn = inr ? __ldg(q   + nsi) : 0;
        fn = inr ? __ldg(fam + nsi) : 0;
    }

    int   sa[5] = { s4.x, s4.y, s4.z, s4.w, sn };
    int   qa[5] = { q4.x, q4.y, q4.z, q4.w, qn };
    int   fa[5] = { f4.x, f4.y, f4.z, f4.w, fn };
    int   ma[4] = { m4.x, m4.y, m4.z, m4.w };
    float la[4] = { l4.x, l4.y, l4.z, l4.w };
    int   va[4] = { v4.x, v4.y, v4.z, v4.w };

    // packed valid nibble for k3 (1 byte per 4 elements; warp writes 32 consecutive bytes)
    g_vb[i0 >> 2] = (unsigned char)((va[0] ? 1 : 0) | (va[1] ? 2 : 0) |
                                    (va[2] ? 4 : 0) | (va[3] ? 8 : 0));

    float so[4], cpo[4];
    #pragma unroll
    for (int k = 0; k < 4; k++) {
        int c6  = ((sa[k]   >> 6) ^ sa[k]  ) & 63;
        int c6n = ((sa[k+1] >> 6) ^ sa[k+1]) & 63;
        float d_chi = (float)__popc(c6 ^ c6n) / 6.0f;
        float d_q   = (float)__popc((qa[k] & 63) ^ (qa[k+1] & 63)) / 6.0f;
        float d_f   = (float)__popc((fa[k] ^ fa[k+1]) & 3) * 0.5f;
        float score = 0.5f*d_chi + 0.35f*d_q + 0.15f*d_f;
        score = fminf(fmaxf(score, 1e-6f), 1.0f);
        bool v = (va[k] != 0);
        so[k] = v ? score : 0.0f;
        float cosine = expf(fminf(la[k], 0.0f));   // accurate expf: feeds threshold path
        float cpv = 0.5f*cosine + 0.5f*so[k];
        cpo[k] = cpv;
        if (v) {
            csum += cpv;
            vpack += vinc;
            int qb = qa[k] & 63;
            int aq = ((qb >> 3) << 7) + lbase + ((qb >> 1) & 3);
            myh[aq] = (unsigned char)(myh[aq] + (1 << ((qb & 1) << 2)));
            int mb = ma[k] & 63;
            int am = 1024 + ((mb >> 3) << 7) + lbase + ((mb >> 1) & 3);
            myh[am] = (unsigned char)(myh[am] + (1 << ((mb & 1) << 2)));
            facc  += 1ull << ((fa[k] & 3) << 4);
            shacc += 1ull << (__popc(c6) * 9);
        }
    }
    *(float4*)(outStruct + i0) = make_float4(so[0], so[1], so[2], so[3]);
    *(float4*)(g_cp + i0)      = make_float4(cpo[0], cpo[1], cpo[2], cpo[3]);
}

// ---------------- K1: structural + cp + atomic-free histograms (2 tiles/thread) ----------------
__global__ __launch_bounds__(TPB, 5) void k1(
    const float* __restrict__ lp, const int* __restrict__ st,
    const int* __restrict__ q,  const int* __restrict__ fam,
    const int* __restrict__ mic, const int* __restrict__ vm,
    float* __restrict__ outStruct, int n)
{
    __shared__ unsigned char wb[8][2048];
    __shared__ int blkH[128];
    __shared__ int sShell[7];
    __shared__ float swC[8];
    __shared__ int   swV[8];
    __shared__ unsigned long long swF[8];

    int t = threadIdx.x, lane = t & 31, wid = t >> 5;
    {   // zero 16KB of nibble counters + small arrays
        unsigned* w32 = (unsigned*)wb;
        #pragma unroll
        for (int i = 0; i < 16; i++) w32[t + i*TPB] = 0u;
        if (t < 128) blkH[t] = 0;
        if (t < 7)   sShell[t] = 0;
    }
    __syncthreads();

    int b = blockIdx.x;
    unsigned char* myh = wb[wid];
    int lbase = lane << 2;

    float csum = 0.f;
    unsigned long long facc = 0ull, shacc = 0ull;
    int vpack = 0;

    // unroll 1: keeps only ONE tile's loads live at a time (register pressure)
    #pragma unroll 1
    for (int h = 0; h < 2; h++) {
        tileWork(b*BE1 + (h << 10) + t*4, n, lane, lp, st, q, fam, mic, vm, outStruct,
                 csum, vpack, 1 << (h << 4), facc, shacc, myh, lbase);
    }

    __syncwarp();
    // per-warp nibble-hist flush (2x16 split keeps per-byte partials <= 128)
    if (lane < 16) {
        const unsigned* wrow = (const unsigned*)wb[wid];
        int rbase = lane * 32;
        unsigned loA = 0u, hiA = 0u, loB = 0u, hiB = 0u;
        #pragma unroll
        for (int w = 0; w < 16; w++) {
            unsigned u = wrow[rbase + ((w + lane) & 31)];
            loA += u & 0x0F0F0F0Fu;
            hiA += (u >> 4) & 0x0F0F0F0Fu;
        }
        #pragma unroll
        for (int w = 16; w < 32; w++) {
            unsigned u = wrow[rbase + ((w + lane) & 31)];
            loB += u & 0x0F0F0F0Fu;
            hiB += (u >> 4) & 0x0F0F0F0Fu;
        }
        int off = (lane < 8) ? 0 : 64;
        int group = lane & 7;
        #pragma unroll
        for (int c = 0; c < 4; c++) {
            int lo = (int)((loA >> (8*c)) & 0xff) + (int)((loB >> (8*c)) & 0xff);
            int hi = (int)((hiA >> (8*c)) & 0xff) + (int)((hiB >> (8*c)) & 0xff);
            atomicAdd(&blkH[off + group*8 + c*2 + 0], lo);
            atomicAdd(&blkH[off + group*8 + c*2 + 1], hi);
        }
    }

    // deterministic per-block reductions (fixed order; csum path deterministic)
    #pragma unroll
    for (int o = 16; o; o >>= 1) {
        csum  += __shfl_down_sync(FULLM, csum,  o);
        vpack += __shfl_down_sync(FULLM, vpack, o);
        facc  += __shfl_down_sync(FULLM, facc,  o);
        shacc += __shfl_down_sync(FULLM, shacc, o);
    }
    if (lane == 0) {
        swC[wid] = csum; swV[wid] = vpack; swF[wid] = facc;
        #pragma unroll
        for (int f = 0; f < 7; f++) {
            int c = (int)((shacc >> (9*f)) & 511ull);
            if (c) atomicAdd(&sShell[f], c);
        }
    }
    __syncthreads();

    // global flush
    if (t < 128) {
        int c = blkH[t];
        if (c) atomicAdd((t < 64) ? &g_qh[t] : &g_mich[t - 64], c);
    }
    if (t < 7) {
        int c = sShell[t];
        if (c) atomicAdd(&g_shellh[t], c);
    }
    if (t == 0) {
        float cs = 0.f; int vp = 0; unsigned long long fs = 0ull;
        for (int w = 0; w < 8; w++) { cs += swC[w]; vp += swV[w]; fs += swF[w]; }
        g_blkC[b] = cs;
        g_blkV[2*b]     = vp & 0xffff;
        g_blkV[2*b + 1] = (vp >> 16) & 0xffff;
        atomicAdd(&g_famh[0], (int)( fs        & 0xffff));
        atomicAdd(&g_famh[1], (int)((fs >> 16) & 0xffff));
        atomicAdd(&g_famh[2], (int)((fs >> 32) & 0xffff));
        atomicAdd(&g_famh[3], (int)((fs >> 48) & 0xffff));
    }
    cudaTriggerProgrammaticLaunchCompletion();
}

// ---------------- K2: 1024 thr, shuffle vpfx scan (int4) + bit-identical csum tree ----------------
__global__ __launch_bounds__(1024) void k2(float* __restrict__ out, int n, int NB1, int NBV) {
    __shared__ int sScan[32];
    __shared__ float sf[1024];
    int t = threadIdx.x, lane = t & 31, wid = t >> 5;

    cudaGridDependencySynchronize();   // wait for k1's writes (PDL)

    // (a) integer vpfx scan: 4 contiguous half-blocks per thread, int4 loads
    int4 v4;
    int bi0 = 4*t;
    if (bi0 + 3 < NBV) {
        v4 = *(const int4*)(g_blkV + bi0);
    } else {
        v4.x = (bi0+0 < NBV) ? g_blkV[bi0+0] : 0;
        v4.y = (bi0+1 < NBV) ? g_blkV[bi0+1] : 0;
        v4.z = (bi0+2 < NBV) ? g_blkV[bi0+2] : 0;
        v4.w = (bi0+3 < NBV) ? g_blkV[bi0+3] : 0;
    }
    int tsum = v4.x + v4.y + v4.z + v4.w;
    int incl = tsum;
    #pragma unroll
    for (int d = 1; d < 32; d <<= 1) {
        int o = __shfl_up_sync(FULLM, incl, d);
        if (lane >= d) incl += o;
    }
    if (lane == 31) sScan[wid] = incl;
    __syncthreads();
    if (wid == 0) {
        int x = sScan[lane];
        #pragma unroll
        for (int d = 1; d < 32; d <<= 1) {
            int o = __shfl_up_sync(FULLM, x, d);
            if (lane >= d) x += o;
        }
        sScan[lane] = x;   // inclusive scan of warp sums
    }
    __syncthreads();
    int woff = wid ? sScan[wid - 1] : 0;
    int run = woff + incl - tsum;
    if (bi0 + 3 < NBV) {
        int4 o4;
        o4.x = run; run += v4.x;
        o4.y = run; run += v4.y;
        o4.z = run; run += v4.z;
        o4.w = run;
        *(int4*)(g_vpfx + bi0) = o4;
    } else {
        if (bi0+0 < NBV) g_vpfx[bi0+0] = run; run += v4.x;
        if (bi0+1 < NBV) g_vpfx[bi0+1] = run; run += v4.y;
        if (bi0+2 < NBV) g_vpfx[bi0+2] = run; run += v4.z;
        if (bi0+3 < NBV) g_vpfx[bi0+3] = run;
    }
    int total = sScan[31];

    // (b) csum tree — BIT-IDENTICAL to the validated 1024-slot pairwise tree
    {
        int b0 = 2*t, b1 = 2*t + 1;
        float c2 = 0.f;
        if (b0 < NB1) c2 += g_blkC[b0];
        if (b1 < NB1) c2 += g_blkC[b1];
        sf[t] = c2;
    }
    __syncthreads();
    for (int d = 512; d; d >>= 1) { if (t < d) sf[t] += sf[t + d]; __syncthreads(); }

    if (t == 0) {
        g_totValid = total;
        float vcf = fmaxf((float)total, 1.0f);
        float cur = sf[0] / vcf;
        cur = fminf(fmaxf(cur, 1e-4f), 1.0f - 1e-4f);
        float tgt = 1.0f / 6.0f;  // 1 / TARGET_BPP (within clip range)
        float shift = (logf(tgt) - log1pf(-tgt)) - (logf(cur) - log1pf(-cur));
        g_E = expf(shift);
        g_cpT = (float)(1.0 / (1.0 + exp((double)shift)));   // sigmoid(-shift)
    }

    // (c) small-hist outputs (K1 fully done per gridsync)
    float* H = out + 3 * (size_t)n;
    if (t < 64)              H[t] = (float)g_qh[t];
    if (t >= 64 && t < 68)   H[t] = (float)g_famh[t - 64];
    if (t >= 128 && t < 192) H[68 + (t - 128)] = (float)g_mich[t - 128];
    if (t >= 256 && t < 263) H[132 + (t - 256)] = (float)g_shellh[t - 256];
    if (t >= 288 && t < 295) {            // q_weight_hist7 from q hist
        int w = t - 288, acc2 = 0;
        for (int qq = 0; qq < 64; qq++) if (__popc(qq) == w) acc2 += g_qh[qq];
        H[139 + w] = (float)acc2;
    }
    if (t >= 320 && t < 326) {            // bit_excitation6 from q hist
        int j = t - 320, acc2 = 0;
        for (int qq = 0; qq < 64; qq++) acc2 += g_qh[qq] * ((qq >> j) & 1);
        H[146 + j] = (float)acc2;
    }
    cudaTriggerProgrammaticLaunchCompletion();
}

// ---------------- K3: combined logprobs, bmask, lengths (lean math, PDL prefetch) ----------------
__global__ __launch_bounds__(TPB) void k3(
    float* __restrict__ outCL, float* __restrict__ outBM, float* __restrict__ outLen,
    int n)
{
    __shared__ int swS[8], swM[8], swB[8];
    __shared__ int s_fi, s_fp;
    int t = threadIdx.x, b = blockIdx.x;
    int lane = t & 31, wid = t >> 5;
    if (t == 0) s_fi = INT_MAX;
    int i0 = b * BE3 + t * 4;

    // ---- pre-sync phase: everything independent of k2 ----
    // (g_vb/g_cp were written by k1, complete before k2's trigger)
    unsigned vmask = g_vb[i0 >> 2];

    int tsum = __popc(vmask);
    int incl = tsum;
    #pragma unroll
    for (int d = 1; d < 32; d <<= 1) {
        int o = __shfl_up_sync(FULLM, incl, d);
        if (lane >= d) incl += o;
    }
    if (lane == 31) swS[wid] = incl;

    float4 c4 = __ldg((const float4*)(g_cp + i0));

    cudaGridDependencySynchronize();   // wait for k2's g_E/g_cpT/g_vpfx (PDL)
    float E   = g_E;
    float cpT = g_cpT;
    int vOff = g_vpfx[b];

    // lean math: sigmoid(logit(cp)+shift) == cp*E / (cp*E + 1-cp); bmask via cp >= cpT
    float ca[4] = { c4.x, c4.y, c4.z, c4.w };
    float clo[4], bmo[4];
    unsigned bvmask = 0;
    #pragma unroll
    for (int k = 0; k < 4; k++) {
        float cpc = fminf(fmaxf(ca[k], 1e-6f), 1.0f - 1e-6f);
        float a = cpc * E;
        float cb = __fdividef(a, a + (1.0f - cpc));
        cb = fminf(fmaxf(cb, 1e-6f), 1.0f - 1e-6f);
        clo[k] = __logf(cb);
        bool bm = (cpc >= cpT);          // exact monotone equivalent of cl >= log(0.5)
        bmo[k] = bm ? 1.0f : 0.0f;
        if (bm && ((vmask >> k) & 1)) bvmask |= 1u << k;
    }
    *(float4*)(outCL + i0) = make_float4(clo[0], clo[1], clo[2], clo[3]);
    *(float4*)(outBM + i0) = make_float4(bmo[0], bmo[1], bmo[2], bmo[3]);

    __syncthreads();   // S1: swS visible
    int blkE = 0;
    for (int w = 0; w < wid; w++) blkE += swS[w];
    int posExcl = vOff + blkE + (incl - tsum);

    // last boundary pos in my segment (pos is nondecreasing => max == last)
    int tlast = 0;
    if (bvmask) {
        int kb = 31 - __clz(bvmask);
        tlast = posExcl + __popc(vmask & ((2u << kb) - 1));
    }
    int im = tlast;
    #pragma unroll
    for (int d = 1; d < 32; d <<= 1) {
        int o = __shfl_up_sync(FULLM, im, d);
        if (lane >= d) im = max(im, o);
    }
    // shuffle executed unconditionally by ALL lanes; select afterwards
    int texm_raw = __shfl_up_sync(FULLM, im, 1);
    int texm = (lane == 0) ? 0 : texm_raw;
    if (lane == 31) swM[wid] = im;

    int bc = __popc(bvmask);
    #pragma unroll
    for (int o = 16; o; o >>= 1) bc += __shfl_down_sync(FULLM, bc, o);
    if (lane == 0) swB[wid] = bc;

    // per-thread first boundary (fixed up with cross-block carry in K4)
    int tfi = INT_MAX, tfp = 0;
    if (bvmask) {
        int kf = __ffs(bvmask) - 1;
        tfi = i0 + kf;
        tfp = posExcl + __popc(vmask & ((2u << kf) - 1));
    }
    atomicMin(&s_fi, tfi);

    __syncthreads();   // S2: swM, swB, s_fi visible
    int blkM = 0;
    for (int w = 0; w < wid; w++) blkM = max(blkM, swM[w]);
    int running = max(blkM, texm);   // exclusive prev (carry=0; first boundary fixed by K4)

    float lo[4];
    #pragma unroll
    for (int k = 0; k < 4; k++) {
        float lenv = 0.0f;
        if ((bvmask >> k) & 1) {
            int posk = posExcl + __popc(vmask & ((2u << k) - 1));
            lenv = (float)(posk - running);
            running = posk;
        }
        lo[k] = lenv;
    }
    // outLen base = out + 3n + 152 floats = 608 bytes: 16B-aligned -> float4 store
    *(float4*)(outLen + i0) = make_float4(lo[0], lo[1], lo[2], lo[3]);

    if (tfi != INT_MAX && tfi == s_fi) s_fp = tfp;

    __syncthreads();   // S3
    if (t == 0) {
        int bl = 0, bcnt = 0;
        for (int w = 0; w < 8; w++) { bl = max(bl, swM[w]); bcnt += swB[w]; }
        g_blkLast[b]     = bl;
        g_blkBvCnt[b]    = bcnt;
        g_blkFirstIdx[b] = (s_fi == INT_MAX) ? -1 : s_fi;
        g_blkFirstPos[b] = (s_fi == INT_MAX) ? 0 : s_fp;
    }
    cudaTriggerProgrammaticLaunchCompletion();
}

// ---------------- K4: 1024 thr, 4/thread int4, shuffle max-scan + scalars + re-zero ----------------
__global__ __launch_bounds__(1024) void k4(float* __restrict__ out, int n, int NBV) {
    __shared__ int sw[32], sb[32];
    int t = threadIdx.x, lane = t & 31, wid = t >> 5;

    cudaGridDependencySynchronize();   // wait for k3's per-block arrays (PDL)

    int bi0 = 4*t;
    int4 l4, b4;
    if (bi0 + 3 < NBV) {
        l4 = *(const int4*)(g_blkLast  + bi0);
        b4 = *(const int4*)(g_blkBvCnt + bi0);
    } else {
        l4.x = (bi0+0 < NBV) ? g_blkLast[bi0+0] : 0;
        l4.y = (bi0+1 < NBV) ? g_blkLast[bi0+1] : 0;
        l4.z = (bi0+2 < NBV) ? g_blkLast[bi0+2] : 0;
        l4.w = (bi0+3 < NBV) ? g_blkLast[bi0+3] : 0;
        b4.x = (bi0+0 < NBV) ? g_blkBvCnt[bi0+0] : 0;
        b4.y = (bi0+1 < NBV) ? g_blkBvCnt[bi0+1] : 0;
        b4.z = (bi0+2 < NBV) ? g_blkBvCnt[bi0+2] : 0;
        b4.w = (bi0+3 < NBV) ? g_blkBvCnt[bi0+3] : 0;
    }
    int bsum = b4.x + b4.y + b4.z + b4.w;
    int m[4];
    int runM = l4.x;         m[0] = runM;
    runM = max(runM, l4.y);  m[1] = runM;
    runM = max(runM, l4.z);  m[2] = runM;
    runM = max(runM, l4.w);  m[3] = runM;

    int inclM = runM;
    #pragma unroll
    for (int d = 1; d < 32; d <<= 1) {
        int o = __shfl_up_sync(FULLM, inclM, d);
        if (lane >= d) inclM = max(inclM, o);
    }
    if (lane == 31) sw[wid] = inclM;
    int bs = bsum;
    #pragma unroll
    for (int o = 16; o; o >>= 1) bs += __shfl_down_sync(FULLM, bs, o);
    if (lane == 0) sb[wid] = bs;
    __syncthreads();

    if (wid == 0) {
        int x = sw[lane];
        #pragma unroll
        for (int d = 1; d < 32; d <<= 1) {
            int o = __shfl_up_sync(FULLM, x, d);
            if (lane >= d) x = max(x, o);
        }
        sw[lane] = x;                       // inclusive max-scan of warp maxima
        int y = sb[lane];
        #pragma unroll
        for (int o = 16; o; o >>= 1) y += __shfl_down_sync(FULLM, y, o);
        if (lane == 0) sb[0] = y;           // total boundary count
    }
    __syncthreads();

    int wprev = wid ? sw[wid - 1] : 0;
    int lprev_raw = __shfl_up_sync(FULLM, inclM, 1);
    int lprev = lane ? lprev_raw : 0;
    int Ex = max(wprev, lprev);             // exclusive max before this thread's 4 blocks

    int4 fi4, fp4;
    if (bi0 + 3 < NBV) {
        fi4 = *(const int4*)(g_blkFirstIdx + bi0);
        fp4 = *(const int4*)(g_blkFirstPos + bi0);
    } else {
        fi4.x = (bi0+0 < NBV) ? g_blkFirstIdx[bi0+0] : -1;
        fi4.y = (bi0+1 < NBV) ? g_blkFirstIdx[bi0+1] : -1;
        fi4.z = (bi0+2 < NBV) ? g_blkFirstIdx[bi0+2] : -1;
        fi4.w = (bi0+3 < NBV) ? g_blkFirstIdx[bi0+3] : -1;
        fp4.x = (bi0+0 < NBV) ? g_blkFirstPos[bi0+0] : 0;
        fp4.y = (bi0+1 < NBV) ? g_blkFirstPos[bi0+1] : 0;
        fp4.z = (bi0+2 < NBV) ? g_blkFirstPos[bi0+2] : 0;
        fp4.w = (bi0+3 < NBV) ? g_blkFirstPos[bi0+3] : 0;
    }
    int fia[4] = { fi4.x, fi4.y, fi4.z, fi4.w };
    int fpa[4] = { fp4.x, fp4.y, fp4.z, fp4.w };
    #pragma unroll
    for (int j = 0; j < 4; j++) {
        if (fia[j] >= 0) {
            int ex = (j > 0) ? max(Ex, m[j-1]) : Ex;
            out[3 * (size_t)n + 152 + fia[j]] = (float)(fpa[j] - ex);
        }
    }

    if (t == 0) {
        int globalLast = sw[31];
        int tv = g_totValid;
        int trailing = tv - globalLast;
        int pc = sb[0] + (trailing > 0 ? 1 : 0);
        out[4 * (size_t)n + 152] = (float)trailing;
        out[4 * (size_t)n + 153] = (float)pc;
    }

    // re-zero global hist accumulators for the next replay of this graph
    // (module load starts them zeroed; every call restores the invariant)
    if (t < 64) { g_qh[t] = 0; g_mich[t] = 0; }
    if (t < 7)  g_shellh[t] = 0;
    if (t < 4)  g_famh[t] = 0;
}

// ---------------- launch ----------------
extern "C" void kernel_launch(void* const* d_in, const int* in_sizes, int n_in,
                              void* d_out, int out_size) {
    const float* lp = (const float*)d_in[0];
    const int* st   = (const int*)d_in[1];
    const int* q    = (const int*)d_in[2];
    const int* fam  = (const int*)d_in[3];
    const int* mic  = (const int*)d_in[4];
    const int* vm   = (const int*)d_in[5];   // bool promoted to int32 by harness
    float* out = (float*)d_out;
    int n = in_sizes[0];            // 4194304
    int NB1 = (n + BE1 - 1) / BE1;  // 2048 k1 blocks
    int NBV = NB1 * 2;              // 4096 half-blocks (= k3 blocks)

    float* outStruct = out + 2 * (size_t)n;
    float* outBM     = out + (size_t)n;
    float* outLen    = out + 3 * (size_t)n + 152;

    cudaLaunchAttribute pdl[1];
    pdl[0].id = cudaLaunchAttributeProgrammaticStreamSerialization;
    pdl[0].val.programmaticStreamSerializationAllowed = 1;

    k1<<<NB1, TPB>>>(lp, st, q, fam, mic, vm, outStruct, n);

    {   // k2 with PDL
        cudaLaunchConfig_t cfg = {};
        cfg.gridDim = dim3(1); cfg.blockDim = dim3(1024);
        cfg.attrs = pdl; cfg.numAttrs = 1;
        cudaLaunchKernelEx(&cfg, k2, out, n, NB1, NBV);
    }
    {   // k3 with PDL
        cudaLaunchConfig_t cfg = {};
        cfg.gridDim = dim3(NBV); cfg.blockDim = dim3(TPB);
        cfg.attrs = pdl; cfg.numAttrs = 1;
        cudaLaunchKernelEx(&cfg, k3, out, outBM, outLen, n);
    }
    {   // k4 with PDL
        cudaLaunchConfig_t cfg = {};
        cfg.gridDim = dim3(1); cfg.blockDim = dim3(1024);
        cfg.attrs = pdl; cfg.numAttrs = 1;
        cudaLaunchKernelEx(&cfg, k4, out, n, NBV);
    }
}